// round 12
// baseline (speedup 1.0000x reference)
#include <cuda_runtime.h>
#include <cstdint>

// Problem constants (fixed by the dataset)
#define NN   10000
#define EE   320000
#define BB   2
#define CINN 64
#define HID  128
#define COUT 128
#define TE   128          // edges per block (= M tile of the edge GEMM)
#define NROW (BB * NN)    // 20000 output rows

// Scratch (device globals: no allocations allowed)
__device__ float    g_a_dst[(size_t)NN * HID];        //  5.12 MB
__device__ float    g_a_src[(size_t)BB * NN * HID];   // 10.24 MB
__device__ float    g_agg  [(size_t)BB * NN * HID];   // 10.24 MB
__device__ float    g_den  [NN];
__device__ uint32_t g_W2p  [16 * 8 * 32 * 4];         // W2 tf32 b-frags (64KB)
__device__ uint32_t g_W3p  [16 * 8 * 32 * 4];         // W3 tf32 b-frags (64KB)

typedef unsigned long long u64;

// ---- packed f32x2 helpers (fma.rn.f32x2 proven on this harness) ----------
__device__ __forceinline__ u64 pk2(float a, float b) {
    u64 r; asm("mov.b64 %0, {%1, %2};" : "=l"(r) : "f"(a), "f"(b)); return r;
}
__device__ __forceinline__ void upk2(u64 v, float& a, float& b) {
    asm("mov.b64 {%0, %1}, %2;" : "=f"(a), "=f"(b) : "l"(v));
}
__device__ __forceinline__ u64 fma2_(u64 a, u64 b, u64 c) {
    u64 d; asm("fma.rn.f32x2 %0, %1, %2, %3;" : "=l"(d) : "l"(a), "l"(b), "l"(c)); return d;
}
__device__ __forceinline__ float tanh_ap(float x) {
    float y; asm("tanh.approx.f32 %0, %1;" : "=f"(y) : "f"(x)); return y;
}
// Packed tanh-gelu: 6 packed FMAs + 2 MUFU per pair of values.
__device__ __forceinline__ u64 gelu2(u64 v) {
    const u64 Z    = pk2(0.0f, 0.0f);
    const u64 K01  = pk2(0.0356774081f, 0.0356774081f);   // k0*k1
    const u64 K0   = pk2(0.7978845608f, 0.7978845608f);
    const u64 HALF = pk2(0.5f, 0.5f);
    const u64 vv  = fma2_(v, v, Z);
    const u64 p   = fma2_(K01, vv, Z);
    const u64 k0v = fma2_(K0, v, Z);
    const u64 u   = fma2_(p, v, k0v);                     // k0(v + k1 v^3)
    float ux, uy; upk2(u, ux, uy);
    const u64 t = pk2(tanh_ap(ux), tanh_ap(uy));
    const u64 w = fma2_(HALF, t, HALF);
    return fma2_(v, w, Z);
}
// Scalar gelu (precompute-free paths don't need it; kept for none) ---------
__device__ __forceinline__ uint32_t f2tf32(float f) {
    uint32_t r; asm("cvt.rna.tf32.f32 %0, %1;" : "=r"(r) : "f"(f)); return r;
}
// mma.sync m16n8k8 tf32 (A row-major frag, B col-major frag, f32 accum)
__device__ __forceinline__ void mma_tf32(float* d, const uint32_t* a, uint32_t b0, uint32_t b1) {
    asm volatile("mma.sync.aligned.m16n8k8.row.col.f32.tf32.tf32.f32 "
                 "{%0,%1,%2,%3}, {%4,%5,%6,%7}, {%8,%9}, {%0,%1,%2,%3};"
                 : "+f"(d[0]), "+f"(d[1]), "+f"(d[2]), "+f"(d[3])
                 : "r"(a[0]), "r"(a[1]), "r"(a[2]), "r"(a[3]), "r"(b0), "r"(b1));
}

// ---------------------------------------------------------------------------
// Prep: pack a 128x128 weight into tf32 B fragments, s-paired, with the
// TRANSPOSED logical-column labeling:  slot (tile t_g, frag col c=l>>2)
// holds W column  n = (t_g>=8)*64 + c*8 + (t_g&7).
// => D col owned by thread q=l&3 for (t, j) is  wn*64 + (2q+j)*8 + t,
//    so each thread owns 16 CONTIGUOUS output columns per D row.
//   b_j(s) = W[k = s*8 + j*4 + (l&3)][n]
// ---------------------------------------------------------------------------
__global__ void wprep_kernel(const float* __restrict__ W, uint32_t* __restrict__ dst) {
    const int idx = blockIdx.x * blockDim.x + threadIdx.x;   // 0..16383 words
    const int q  = idx & 3;
    const int l  = (idx >> 2) & 31;
    const int sp = (idx >> 7) & 7;
    const int t  = idx >> 10;                                 // 0..15
    const int j  = q & 1;
    const int s  = sp * 2 + (q >> 1);
    const int k  = s * 8 + j * 4 + (l & 3);
    const int n  = (t >> 3) * 64 + (l >> 2) * 8 + (t & 7);    // transposed labels
    dst[idx] = f2tf32(W[k * HID + n]);
}

// ---------------------------------------------------------------------------
// Per-node precompute (also zeroes g_agg / g_den):
//   a_dst[n]   = pos[n] @ W1[0:3]
//   a_src[b,n] = pos[n] @ W1[3:6] + x[b,n] @ W1[6:70] + b1
//   out[b,n]   = x[b,n] @ Ws + bs   (skip path; final adds)
// ---------------------------------------------------------------------------
__global__ void precompute_kernel(const float* __restrict__ x, const float* __restrict__ pos,
                                  const float* __restrict__ W1, const float* __restrict__ b1,
                                  const float* __restrict__ Ws, const float* __restrict__ bs,
                                  float* __restrict__ out) {
    const int blk = blockIdx.x;          // b*NN + n
    const int b   = blk / NN;
    const int n   = blk - b * NN;
    const int t   = threadIdx.x;         // 0..127
    __shared__ float xr[CINN];
    __shared__ float p3[3];
    if (t < CINN) xr[t] = x[(size_t)blk * CINN + t];
    if (t < 3)    p3[t] = pos[n * 3 + t];

    g_agg[(size_t)blk * HID + t] = 0.0f;
    if (b == 0 && t == 0) g_den[n] = 0.0f;
    __syncthreads();

    float s = b1[t];
#pragma unroll
    for (int j = 0; j < 3; ++j) s += p3[j] * W1[(3 + j) * HID + t];
#pragma unroll 8
    for (int c = 0; c < CINN; ++c) s += xr[c] * W1[(6 + c) * HID + t];
    g_a_src[(size_t)blk * HID + t] = s;

    if (b == 0) {
        float d = p3[0] * W1[0 * HID + t] + p3[1] * W1[1 * HID + t] + p3[2] * W1[2 * HID + t];
        g_a_dst[(size_t)n * HID + t] = d;
    }

    float sk = bs[t];
#pragma unroll 8
    for (int c = 0; c < CINN; ++c) sk += xr[c] * Ws[c * COUT + t];
    out[(size_t)blk * COUT + t] = sk;
}

// ---------------------------------------------------------------------------
// Edge-kernel A layout (s-XORed swizzle, warp-per-edge fill) — as R11:
//   word(g,s,r,kk) = (g*16+s)*128 + ((chunk ^ (s&7))<<2) + slot
//     chunk = (r&7)*4 + ((kk&3) ^ (((r&7)>>1)&3)) ;  slot = (r>>3)*2 + (kk>>2)
// ---------------------------------------------------------------------------
__device__ __forceinline__ int frag_chunk_r(int lane) {
    return (lane >> 2) * 4 + ((lane & 3) ^ (((lane >> 2) >> 1) & 3));
}

// ---------------------------------------------------------------------------
// Edge kernel (mma.sync tf32). Per block: 128 edges, 256 threads (8 warps).
// SMEM: A frags 64KB + staging -> 2 CTAs/SM (phase overlap).
// ---------------------------------------------------------------------------
#define EDGE_SMEM (65536 + 512 + 512 + 512)
__global__ void __launch_bounds__(256, 2)
edge_kernel(const int* __restrict__ eidx, const float* __restrict__ ew,
            const float* __restrict__ b2) {
    extern __shared__ char sm[];
    uint32_t* A_s  = (uint32_t*)sm;                 // [8 g][16 s][128 words]
    float*    b2s  = (float*)   (sm + 65536);
    float*    ews  = (float*)   (sm + 66048);
    int*      dsts = (int*)     (sm + 66560);
    const int tid = threadIdx.x;
    const int e0  = blockIdx.x * TE;
    const int b   = blockIdx.y;

    if (tid < TE) {
        b2s[tid]  = b2[tid];
        const float w = ew[e0 + tid];
        const int   d = eidx[EE + e0 + tid];
        ews[tid]  = w;
        dsts[tid] = d;
        if (b == 0) atomicAdd(&g_den[d], w);        // fused den kernel
    }

    // Fill A fragments: one edge per warp iteration, fully coalesced gathers.
    {
        const int lane = tid & 31;
        const int w    = tid >> 5;                  // warp = fragment group g
        const int s    = lane >> 1;                 // s-step owned by this lane
        const int h    = lane & 1;                  // k-half (kk>>2)
        const int s7   = s & 7;
        uint32_t* srow = A_s + (w * 16 + s) * 128 + h;
        const int eb   = e0 + w * 16;
#pragma unroll 4
        for (int it = 0; it < 16; ++it) {
            const int sv = __ldg(eidx + eb + it);            // warp-uniform
            const int dv = __ldg(eidx + EE + eb + it);       // warp-uniform
            const float4 D = __ldg((const float4*)(g_a_dst + (size_t)dv * HID) + lane);
            const float4 S = __ldg((const float4*)(g_a_src + ((size_t)b * NN + sv) * HID) + lane);
            const int r7  = it & 7;
            const int rh2 = (it >> 3) * 2;
            const int swz = (r7 >> 1) & 3;
            const int cb  = r7 * 4;
            const u64 ONE = pk2(1.0f, 1.0f);
            const u64 g0 = gelu2(fma2_(pk2(D.x, D.y), ONE, pk2(S.x, S.y)));
            const u64 g1 = gelu2(fma2_(pk2(D.z, D.w), ONE, pk2(S.z, S.w)));
            float a0, a1, a2, a3; upk2(g0, a0, a1); upk2(g1, a2, a3);
            srow[(((cb + (0 ^ swz)) ^ s7) << 2) + rh2] = f2tf32(a0);
            srow[(((cb + (1 ^ swz)) ^ s7) << 2) + rh2] = f2tf32(a1);
            srow[(((cb + (2 ^ swz)) ^ s7) << 2) + rh2] = f2tf32(a2);
            srow[(((cb + (3 ^ swz)) ^ s7) << 2) + rh2] = f2tf32(a3);
        }
    }
    __syncthreads();

    // GEMM: warp (wm, wn) -> edges [wm*32,+32), cols [wn*64,+64)
    const int lane = tid & 31;
    const int w    = tid >> 5;
    const int wm   = w & 3;
    const int wn   = w >> 2;
    const int fcr  = frag_chunk_r(lane);
    float acc[2][8][4];
#pragma unroll
    for (int g = 0; g < 2; ++g)
#pragma unroll
        for (int t = 0; t < 8; ++t)
#pragma unroll
            for (int q = 0; q < 4; ++q) acc[g][t][q] = 0.0f;

    const uint4* __restrict__ Bg4 = (const uint4*)g_W2p;

#pragma unroll
    for (int sp = 0; sp < 8; ++sp) {
        const int s0 = sp * 2;
        const int x0 = (fcr ^ (s0 & 7)) << 2;       // s0 even -> s1 ofs = x0^4
        uint32_t a[2][2][4];
#pragma unroll
        for (int gg = 0; gg < 2; ++gg) {
            const int g = wm * 2 + gg;
            const uint4 v0 = *(const uint4*)(A_s + (g * 16 + s0) * 128 + x0);
            const uint4 v1 = *(const uint4*)(A_s + (g * 16 + s0 + 1) * 128 + (x0 ^ 4));
            a[gg][0][0] = v0.x; a[gg][0][1] = v0.z; a[gg][0][2] = v0.y; a[gg][0][3] = v0.w;
            a[gg][1][0] = v1.x; a[gg][1][1] = v1.z; a[gg][1][2] = v1.y; a[gg][1][3] = v1.w;
        }
#pragma unroll
        for (int t = 0; t < 8; ++t) {
            const uint4 bv = __ldg(Bg4 + ((wn * 8 + t) * 8 + sp) * 32 + lane);
            mma_tf32(acc[0][t], a[0][0], bv.x, bv.y);
            mma_tf32(acc[1][t], a[1][0], bv.x, bv.y);
            mma_tf32(acc[0][t], a[0][1], bv.z, bv.w);
            mma_tf32(acc[1][t], a[1][1], bv.z, bv.w);
        }
    }

    // Epilogue (transposed labels): thread q owns 16 contiguous cols per row
    // -> 4x red.global.add.v4 per (g, rh), packed gelu on value pairs.
    const float4* b2p = (const float4*)(b2s + wn * 64 + 16 * (lane & 3));
    float4 b2q[4];
#pragma unroll
    for (int i = 0; i < 4; ++i) b2q[i] = b2p[i];
    const u64 ONE = pk2(1.0f, 1.0f);
    const u64 Z   = pk2(0.0f, 0.0f);

#pragma unroll
    for (int g = 0; g < 2; ++g) {
#pragma unroll
        for (int rh = 0; rh < 2; ++rh) {
            const int m   = wm * 32 + g * 16 + rh * 8 + (lane >> 2);
            const float wgt = ews[m];
            const u64 w2 = pk2(wgt, wgt);
            float* base = g_agg + ((size_t)b * NN + dsts[m]) * HID
                          + wn * 64 + 16 * (lane & 3);
#pragma unroll
            for (int half = 0; half < 2; ++half) {
                const int c = rh * 2 + half;
#pragma unroll
                for (int tq = 0; tq < 2; ++tq) {
                    const float4 bb = b2q[half * 2 + tq];
                    const u64 v01 = fma2_(pk2(acc[g][tq * 4 + 0][c], acc[g][tq * 4 + 1][c]),
                                          ONE, pk2(bb.x, bb.y));
                    const u64 v23 = fma2_(pk2(acc[g][tq * 4 + 2][c], acc[g][tq * 4 + 3][c]),
                                          ONE, pk2(bb.z, bb.w));
                    const u64 r01 = fma2_(gelu2(v01), w2, Z);
                    const u64 r23 = fma2_(gelu2(v23), w2, Z);
                    float r0, r1, r2, r3; upk2(r01, r0, r1); upk2(r23, r2, r3);
                    asm volatile("red.global.add.v4.f32 [%0], {%1,%2,%3,%4};"
                                 :: "l"(base + half * 8 + tq * 4),
                                    "f"(r0), "f"(r1), "f"(r2), "f"(r3) : "memory");
                }
            }
        }
    }
}

// ---------------------------------------------------------------------------
// Final kernel (mma.sync tf32): out[row] += (agg[row] @ W3 + den*b3)/(den+eps)
// 128 rows per block, 256 threads; transposed labels -> float4 RMW epilogue.
// ---------------------------------------------------------------------------
#define FIN_SMEM (65536 + 512 + 512)
__global__ void __launch_bounds__(256, 2)
final_kernel(const float* __restrict__ b3, float* __restrict__ out) {
    extern __shared__ char sm[];
    uint32_t* A_s  = (uint32_t*)sm;                 // [8 g][16 s][128 words]
    float*    b3s  = (float*)(sm + 65536);
    float*    dens = (float*)(sm + 66048);
    const int tid = threadIdx.x;
    const int r0  = blockIdx.x * 128;

    if (tid < 128) {
        b3s[tid] = b3[tid];
        const int row = r0 + tid;
        dens[tid] = (row < NROW) ? g_den[row % NN] : 0.0f;
    }

    // Fill A fragments from g_agg rows (old non-XOR layout, 2 threads/row)
    {
        const int m   = tid >> 1;
        const int h   = tid & 1;
        const int row = r0 + m;
        const bool ok = (row < NROW);
        const int g  = m >> 4;
        const int r  = m & 15;
        const int r7 = r & 7;
        const int rh = r >> 3;
        const int swz = (r7 >> 1) & 3;
        int offs[4];
#pragma unroll
        for (int j = 0; j < 4; ++j)
            offs[j] = (r7 * 4 + (j ^ swz)) * 4 + rh * 2 + h;
        const float4* pa4 = (const float4*)(g_agg + (size_t)(ok ? row : 0) * HID);
#pragma unroll
        for (int i = 0; i < 16; ++i) {
            float4 A0 = pa4[2 * i + h];
            if (!ok) A0 = make_float4(0, 0, 0, 0);
            uint32_t* rowp = A_s + (g * 16 + i) * 128;
            rowp[offs[0]] = f2tf32(A0.x);
            rowp[offs[1]] = f2tf32(A0.y);
            rowp[offs[2]] = f2tf32(A0.z);
            rowp[offs[3]] = f2tf32(A0.w);
        }
    }
    __syncthreads();

    const int lane = tid & 31;
    const int w    = tid >> 5;
    const int wm   = w & 3;
    const int wn   = w >> 2;
    const int ckr  = frag_chunk_r(lane) * 4;
    float acc[2][8][4];
#pragma unroll
    for (int g = 0; g < 2; ++g)
#pragma unroll
        for (int t = 0; t < 8; ++t)
#pragma unroll
            for (int q = 0; q < 4; ++q) acc[g][t][q] = 0.0f;

    const uint4* __restrict__ Bg4 = (const uint4*)g_W3p;

#pragma unroll
    for (int sp = 0; sp < 8; ++sp) {
        const int s0 = sp * 2;
        uint32_t a[2][2][4];
#pragma unroll
        for (int gg = 0; gg < 2; ++gg) {
            const int g = wm * 2 + gg;
            const uint4 v0 = *(const uint4*)(A_s + (g * 16 + s0) * 128 + ckr);
            const uint4 v1 = *(const uint4*)(A_s + (g * 16 + s0 + 1) * 128 + ckr);
            a[gg][0][0] = v0.x; a[gg][0][1] = v0.z; a[gg][0][2] = v0.y; a[gg][0][3] = v0.w;
            a[gg][1][0] = v1.x; a[gg][1][1] = v1.z; a[gg][1][2] = v1.y; a[gg][1][3] = v1.w;
        }
#pragma unroll
        for (int t = 0; t < 8; ++t) {
            const uint4 bv = __ldg(Bg4 + ((wn * 8 + t) * 8 + sp) * 32 + lane);
            mma_tf32(acc[0][t], a[0][0], bv.x, bv.y);
            mma_tf32(acc[1][t], a[1][0], bv.x, bv.y);
            mma_tf32(acc[0][t], a[0][1], bv.z, bv.w);
            mma_tf32(acc[1][t], a[1][1], bv.z, bv.w);
        }
    }

    // Epilogue: out += (acc + den*b3)/(den+eps) on contiguous 16-col runs
    const float4* b3p = (const float4*)(b3s + wn * 64 + 16 * (lane & 3));
    float4 b3q[4];
#pragma unroll
    for (int i = 0; i < 4; ++i) b3q[i] = b3p[i];

#pragma unroll
    for (int g = 0; g < 2; ++g) {
#pragma unroll
        for (int rh = 0; rh < 2; ++rh) {
            const int m   = wm * 32 + g * 16 + rh * 8 + (lane >> 2);
            const int row = r0 + m;
            if (row < NROW) {
                const float den = dens[m];
                const float inv = 1.0f / (den + 1e-12f);
                float* op = out + (size_t)row * COUT + wn * 64 + 16 * (lane & 3);
#pragma unroll
                for (int half = 0; half < 2; ++half) {
                    const int c = rh * 2 + half;
#pragma unroll
                    for (int tq = 0; tq < 2; ++tq) {
                        const float4 bb = b3q[half * 2 + tq];
                        float4 o = *(float4*)(op + half * 8 + tq * 4);
                        o.x += (acc[g][tq * 4 + 0][c] + den * bb.x) * inv;
                        o.y += (acc[g][tq * 4 + 1][c] + den * bb.y) * inv;
                        o.z += (acc[g][tq * 4 + 2][c] + den * bb.z) * inv;
                        o.w += (acc[g][tq * 4 + 3][c] + den * bb.w) * inv;
                        *(float4*)(op + half * 8 + tq * 4) = o;
                    }
                }
            }
        }
    }
}

// ---------------------------------------------------------------------------
extern "C" void kernel_launch(void* const* d_in, const int* in_sizes, int n_in,
                              void* d_out, int out_size) {
    const float* x   = (const float*)d_in[0];
    const float* pos = (const float*)d_in[1];
    const int*   ei  = (const int*)  d_in[2];
    const float* ew  = (const float*)d_in[3];
    const float* W1  = (const float*)d_in[4];
    const float* b1  = (const float*)d_in[5];
    const float* W2  = (const float*)d_in[6];
    const float* b2  = (const float*)d_in[7];
    const float* W3  = (const float*)d_in[8];
    const float* b3  = (const float*)d_in[9];
    const float* Ws  = (const float*)d_in[10];
    const float* bs  = (const float*)d_in[11];
    float* out = (float*)d_out;

    uint32_t* w2p; cudaGetSymbolAddress((void**)&w2p, g_W2p);
    uint32_t* w3p; cudaGetSymbolAddress((void**)&w3p, g_W3p);

    cudaFuncSetAttribute(edge_kernel,  cudaFuncAttributeMaxDynamicSharedMemorySize, EDGE_SMEM);
    cudaFuncSetAttribute(final_kernel, cudaFuncAttributeMaxDynamicSharedMemorySize, FIN_SMEM);

    wprep_kernel<<<64, 256>>>(W2, w2p);
    wprep_kernel<<<64, 256>>>(W3, w3p);
    precompute_kernel<<<NROW, HID>>>(x, pos, W1, b1, Ws, bs, out);
    edge_kernel<<<dim3(EE / TE, BB), 256, EDGE_SMEM>>>(ei, ew, b2);
    final_kernel<<<(NROW + 127) / 128, 256, FIN_SMEM>>>(b3, out);
}

// round 13
// speedup vs baseline: 1.2123x; 1.2123x over previous
#include <cuda_runtime.h>
#include <cstdint>

// Problem constants (fixed by the dataset)
#define NN   10000
#define EE   320000
#define BB   2
#define CINN 64
#define HID  128
#define COUT 128
#define TE   128          // edges per block (= M tile of the edge GEMM)
#define NROW (BB * NN)    // 20000 output rows

// Scratch (device globals: no allocations allowed)
__device__ float    g_a_dst[(size_t)NN * HID];        //  5.12 MB
__device__ float    g_a_src[(size_t)BB * NN * HID];   // 10.24 MB
__device__ float    g_agg  [(size_t)BB * NN * HID];   // 10.24 MB
__device__ float    g_den  [NN];
__device__ uint32_t g_W2pb [16 * 4 * 32 * 4];         // W2 bf16 b-frags (32KB)
__device__ uint32_t g_W3p  [16 * 8 * 32 * 4];         // W3 tf32 b-frags (64KB)

typedef unsigned long long u64;

// ---- packed f32x2 helpers ------------------------------------------------
__device__ __forceinline__ u64 pk2(float a, float b) {
    u64 r; asm("mov.b64 %0, {%1, %2};" : "=l"(r) : "f"(a), "f"(b)); return r;
}
__device__ __forceinline__ void upk2(u64 v, float& a, float& b) {
    asm("mov.b64 {%0, %1}, %2;" : "=f"(a), "=f"(b) : "l"(v));
}
__device__ __forceinline__ u64 fma2_(u64 a, u64 b, u64 c) {
    u64 d; asm("fma.rn.f32x2 %0, %1, %2, %3;" : "=l"(d) : "l"(a), "l"(b), "l"(c)); return d;
}
__device__ __forceinline__ float tanh_ap(float x) {
    float y; asm("tanh.approx.f32 %0, %1;" : "=f"(y) : "f"(x)); return y;
}
// Packed tanh-gelu: 6 packed FMAs + 2 MUFU per pair of values.
__device__ __forceinline__ u64 gelu2(u64 v) {
    const u64 Z    = pk2(0.0f, 0.0f);
    const u64 K01  = pk2(0.0356774081f, 0.0356774081f);   // k0*k1
    const u64 K0   = pk2(0.7978845608f, 0.7978845608f);
    const u64 HALF = pk2(0.5f, 0.5f);
    const u64 vv  = fma2_(v, v, Z);
    const u64 p   = fma2_(K01, vv, Z);
    const u64 k0v = fma2_(K0, v, Z);
    const u64 u   = fma2_(p, v, k0v);                     // k0(v + k1 v^3)
    float ux, uy; upk2(u, ux, uy);
    const u64 t = pk2(tanh_ap(ux), tanh_ap(uy));
    const u64 w = fma2_(HALF, t, HALF);
    return fma2_(v, w, Z);
}
__device__ __forceinline__ uint32_t f2tf32(float f) {
    uint32_t r; asm("cvt.rna.tf32.f32 %0, %1;" : "=r"(r) : "f"(f)); return r;
}
// pack {lo, hi} floats -> bf16x2 word (first PTX operand is the HIGH half)
__device__ __forceinline__ uint32_t bf2(float lo, float hi) {
    uint32_t r; asm("cvt.rn.bf16x2.f32 %0, %1, %2;" : "=r"(r) : "f"(hi), "f"(lo)); return r;
}
// mma m16n8k16 bf16 (A row frag a0..a3, B col frag b0,b1; f32 accum)
__device__ __forceinline__ void mma_bf16(float* d, uint32_t a0, uint32_t a1,
                                         uint32_t a2, uint32_t a3,
                                         uint32_t b0, uint32_t b1) {
    asm volatile("mma.sync.aligned.m16n8k16.row.col.f32.bf16.bf16.f32 "
                 "{%0,%1,%2,%3}, {%4,%5,%6,%7}, {%8,%9}, {%0,%1,%2,%3};"
                 : "+f"(d[0]), "+f"(d[1]), "+f"(d[2]), "+f"(d[3])
                 : "r"(a0), "r"(a1), "r"(a2), "r"(a3), "r"(b0), "r"(b1));
}
// mma m16n8k8 tf32 (kept for final_kernel)
__device__ __forceinline__ void mma_tf32(float* d, const uint32_t* a, uint32_t b0, uint32_t b1) {
    asm volatile("mma.sync.aligned.m16n8k8.row.col.f32.tf32.tf32.f32 "
                 "{%0,%1,%2,%3}, {%4,%5,%6,%7}, {%8,%9}, {%0,%1,%2,%3};"
                 : "+f"(d[0]), "+f"(d[1]), "+f"(d[2]), "+f"(d[3])
                 : "r"(a[0]), "r"(a[1]), "r"(a[2]), "r"(a[3]), "r"(b0), "r"(b1));
}

// ---------------------------------------------------------------------------
// W2 bf16 fragment prep (transposed column labels, same as R12):
//   uint4 (t, sp, l) = { b0(s=2sp), b1(2sp), b0(2sp+1), b1(2sp+1) }, s = k16 step
//   b_j(s) lane l = bf16x2 of W[k0][n], W[k0+1][n],
//     k0 = s*16 + j*8 + (l&3)*2 ;  n = (t>>3)*64 + (l>>2)*8 + (t&7)
// ---------------------------------------------------------------------------
__global__ void w2prep_bf16(const float* __restrict__ W, uint32_t* __restrict__ dst) {
    const int idx = blockIdx.x * blockDim.x + threadIdx.x;   // 0..8191
    const int q  = idx & 3;
    const int l  = (idx >> 2) & 31;
    const int sp = (idx >> 7) & 3;
    const int t  = idx >> 9;                                  // 0..15
    const int j  = q & 1;
    const int s  = sp * 2 + (q >> 1);
    const int k0 = s * 16 + j * 8 + (l & 3) * 2;
    const int n  = (t >> 3) * 64 + (l >> 2) * 8 + (t & 7);
    dst[idx] = bf2(W[k0 * HID + n], W[(k0 + 1) * HID + n]);
}

// ---------------------------------------------------------------------------
// W3 tf32 fragment prep (unchanged from R12, transposed labels)
// ---------------------------------------------------------------------------
__global__ void wprep_kernel(const float* __restrict__ W, uint32_t* __restrict__ dst) {
    const int idx = blockIdx.x * blockDim.x + threadIdx.x;   // 0..16383 words
    const int q  = idx & 3;
    const int l  = (idx >> 2) & 31;
    const int sp = (idx >> 7) & 7;
    const int t  = idx >> 10;                                 // 0..15
    const int j  = q & 1;
    const int s  = sp * 2 + (q >> 1);
    const int k  = s * 8 + j * 4 + (l & 3);
    const int n  = (t >> 3) * 64 + (l >> 2) * 8 + (t & 7);
    dst[idx] = f2tf32(W[k * HID + n]);
}

// ---------------------------------------------------------------------------
// Per-node precompute (also zeroes g_agg / g_den) — unchanged
// ---------------------------------------------------------------------------
__global__ void precompute_kernel(const float* __restrict__ x, const float* __restrict__ pos,
                                  const float* __restrict__ W1, const float* __restrict__ b1,
                                  const float* __restrict__ Ws, const float* __restrict__ bs,
                                  float* __restrict__ out) {
    const int blk = blockIdx.x;          // b*NN + n
    const int b   = blk / NN;
    const int n   = blk - b * NN;
    const int t   = threadIdx.x;         // 0..127
    __shared__ float xr[CINN];
    __shared__ float p3[3];
    if (t < CINN) xr[t] = x[(size_t)blk * CINN + t];
    if (t < 3)    p3[t] = pos[n * 3 + t];

    g_agg[(size_t)blk * HID + t] = 0.0f;
    if (b == 0 && t == 0) g_den[n] = 0.0f;
    __syncthreads();

    float s = b1[t];
#pragma unroll
    for (int j = 0; j < 3; ++j) s += p3[j] * W1[(3 + j) * HID + t];
#pragma unroll 8
    for (int c = 0; c < CINN; ++c) s += xr[c] * W1[(6 + c) * HID + t];
    g_a_src[(size_t)blk * HID + t] = s;

    if (b == 0) {
        float d = p3[0] * W1[0 * HID + t] + p3[1] * W1[1 * HID + t] + p3[2] * W1[2 * HID + t];
        g_a_dst[(size_t)n * HID + t] = d;
    }

    float sk = bs[t];
#pragma unroll 8
    for (int c = 0; c < CINN; ++c) sk += xr[c] * Ws[c * COUT + t];
    out[(size_t)blk * COUT + t] = sk;
}

// ---------------------------------------------------------------------------
// bf16 A-smem layout (32KB): row m (0..127) x 64 bf16x2 words.
//   logical word w = k/2; stored index SW = s*8 + off*2 + h
//     where k = 16s + 8h + 2off (s = w>>3, h = (w>>2)&1, off = w&3)
//   swizzle: addr = m*64 + (SW ^ c(m)),  c(m) = ((m&3)<<3) | (((m>>2)&1)<<2)
// Reader (warp GEMM): (a0,a2) = one LDS.64 at row R, (a1,a3) at row R+8;
//   16-lane phases hit 16 distinct double-banks (conflict-free).
// Writer (warp-per-edge): lane l stores words w=2l,2l+1 as 2x STS.32.
// ---------------------------------------------------------------------------
__device__ __forceinline__ int frag_chunk_r(int lane) {   // final_kernel only
    return (lane >> 2) * 4 + ((lane & 3) ^ (((lane >> 2) >> 1) & 3));
}

// ---------------------------------------------------------------------------
// Edge kernel (mma.sync bf16 k16). 128 edges/block, 256 threads, 2 CTAs/SM.
// SMEM: A 32KB + staging ~1.5KB.
// ---------------------------------------------------------------------------
#define EDGE_SMEM (32768 + 512 + 512 + 512)
__global__ void __launch_bounds__(256, 2)
edge_kernel(const int* __restrict__ eidx, const float* __restrict__ ew,
            const float* __restrict__ b2) {
    extern __shared__ char sm[];
    uint32_t* A_s  = (uint32_t*)sm;                 // [128 m][64 words]
    float*    b2s  = (float*)   (sm + 32768);
    float*    ews  = (float*)   (sm + 33280);
    int*      dsts = (int*)     (sm + 33792);
    const int tid = threadIdx.x;
    const int e0  = blockIdx.x * TE;
    const int b   = blockIdx.y;

    if (tid < TE) {
        b2s[tid]  = b2[tid];
        const float w = ew[e0 + tid];
        const int   d = eidx[EE + e0 + tid];
        ews[tid]  = w;
        dsts[tid] = d;
        if (b == 0) atomicAdd(&g_den[d], w);        // fused den kernel
    }

    // Fill A: one edge per warp iteration, coalesced 512B row gathers.
    {
        const int lane = tid & 31;
        const int w    = tid >> 5;
        // stored word indices for logical words 2l (->a0,a1 pair) and 2l+1 (->a2,a3)
        const int W0 = 8 * (lane >> 2) + 4 * (lane & 1) + ((lane >> 1) & 1);
        const int eb = e0 + w * 16;
#pragma unroll 4
        for (int it = 0; it < 16; ++it) {
            const int m  = w * 16 + it;
            const int sv = __ldg(eidx + eb + it);            // warp-uniform
            const int dv = __ldg(eidx + EE + eb + it);       // warp-uniform
            const float4 D = __ldg((const float4*)(g_a_dst + (size_t)dv * HID) + lane);
            const float4 S = __ldg((const float4*)(g_a_src + ((size_t)b * NN + sv) * HID) + lane);
            const u64 ONE = pk2(1.0f, 1.0f);
            const u64 g0 = gelu2(fma2_(pk2(D.x, D.y), ONE, pk2(S.x, S.y)));
            const u64 g1 = gelu2(fma2_(pk2(D.z, D.w), ONE, pk2(S.z, S.w)));
            float a0, a1, a2, a3; upk2(g0, a0, a1); upk2(g1, a2, a3);
            const int cm = ((m & 3) << 3) | (((m >> 2) & 1) << 2);
            uint32_t* rowp = A_s + m * 64;
            rowp[(W0 + 0) ^ cm] = bf2(a0, a1);   // logical word 2l  (k = 4l,4l+1)
            rowp[(W0 + 2) ^ cm] = bf2(a2, a3);   // logical word 2l+1
        }
    }
    __syncthreads();

    // GEMM: warp (wm, wn) -> edges [wm*32,+32), cols [wn*64,+64); k16 steps
    const int lane = tid & 31;
    const int w    = tid >> 5;
    const int wm   = w & 3;
    const int wn   = w >> 2;
    const int fv   = lane >> 2;                     // row-in-group 0..7
    const int foff = lane & 3;
    const int cv   = ((fv & 3) << 3) | ((fv >> 2) << 2);
    float acc[2][8][4];
#pragma unroll
    for (int g = 0; g < 2; ++g)
#pragma unroll
        for (int t = 0; t < 8; ++t)
#pragma unroll
            for (int q = 0; q < 4; ++q) acc[g][t][q] = 0.0f;

    const uint4* __restrict__ Bg4 = (const uint4*)g_W2pb;

#pragma unroll
    for (int sp = 0; sp < 4; ++sp) {
        uint4 bv[8];
#pragma unroll
        for (int t = 0; t < 8; ++t)
            bv[t] = __ldg(Bg4 + ((wn * 8 + t) * 4 + sp) * 32 + lane);
#pragma unroll
        for (int sh = 0; sh < 2; ++sh) {
            const int s = sp * 2 + sh;
            const int swrd = (s * 8 + foff * 2) ^ cv;
            uint2 va[2], vb[2];
#pragma unroll
            for (int gg = 0; gg < 2; ++gg) {
                const int R = wm * 32 + gg * 16 + fv;
                va[gg] = *(const uint2*)(A_s + R * 64 + swrd);          // {a0,a2}
                vb[gg] = *(const uint2*)(A_s + (R + 8) * 64 + swrd);    // {a1,a3}
            }
#pragma unroll
            for (int t = 0; t < 8; ++t) {
                const uint32_t b0 = sh ? bv[t].z : bv[t].x;
                const uint32_t b1 = sh ? bv[t].w : bv[t].y;
                mma_bf16(acc[0][t], va[0].x, vb[0].x, va[0].y, vb[0].y, b0, b1);
                mma_bf16(acc[1][t], va[1].x, vb[1].x, va[1].y, vb[1].y, b0, b1);
            }
        }
    }

    // Epilogue (unchanged from R12): packed gelu + red.global.add.v4
    const float4* b2p = (const float4*)(b2s + wn * 64 + 16 * (lane & 3));
    float4 b2q[4];
#pragma unroll
    for (int i = 0; i < 4; ++i) b2q[i] = b2p[i];
    const u64 ONE = pk2(1.0f, 1.0f);
    const u64 Z   = pk2(0.0f, 0.0f);

#pragma unroll
    for (int g = 0; g < 2; ++g) {
#pragma unroll
        for (int rh = 0; rh < 2; ++rh) {
            const int m   = wm * 32 + g * 16 + rh * 8 + (lane >> 2);
            const float wgt = ews[m];
            const u64 w2 = pk2(wgt, wgt);
            float* base = g_agg + ((size_t)b * NN + dsts[m]) * HID
                          + wn * 64 + 16 * (lane & 3);
#pragma unroll
            for (int half = 0; half < 2; ++half) {
                const int c = rh * 2 + half;
#pragma unroll
                for (int tq = 0; tq < 2; ++tq) {
                    const float4 bb = b2q[half * 2 + tq];
                    const u64 v01 = fma2_(pk2(acc[g][tq * 4 + 0][c], acc[g][tq * 4 + 1][c]),
                                          ONE, pk2(bb.x, bb.y));
                    const u64 v23 = fma2_(pk2(acc[g][tq * 4 + 2][c], acc[g][tq * 4 + 3][c]),
                                          ONE, pk2(bb.z, bb.w));
                    const u64 r01 = fma2_(gelu2(v01), w2, Z);
                    const u64 r23 = fma2_(gelu2(v23), w2, Z);
                    float r0, r1, r2, r3; upk2(r01, r0, r1); upk2(r23, r2, r3);
                    asm volatile("red.global.add.v4.f32 [%0], {%1,%2,%3,%4};"
                                 :: "l"(base + half * 8 + tq * 4),
                                    "f"(r0), "f"(r1), "f"(r2), "f"(r3) : "memory");
                }
            }
        }
    }
}

// ---------------------------------------------------------------------------
// Final kernel (tf32, unchanged from R12): out += (agg @ W3 + den*b3)/(den+eps)
// ---------------------------------------------------------------------------
#define FIN_SMEM (65536 + 512 + 512)
__global__ void __launch_bounds__(256, 2)
final_kernel(const float* __restrict__ b3, float* __restrict__ out) {
    extern __shared__ char sm[];
    uint32_t* A_s  = (uint32_t*)sm;                 // [8 g][16 s][128 words]
    float*    b3s  = (float*)(sm + 65536);
    float*    dens = (float*)(sm + 66048);
    const int tid = threadIdx.x;
    const int r0  = blockIdx.x * 128;

    if (tid < 128) {
        b3s[tid] = b3[tid];
        const int row = r0 + tid;
        dens[tid] = (row < NROW) ? g_den[row % NN] : 0.0f;
    }

    {
        const int m   = tid >> 1;
        const int h   = tid & 1;
        const int row = r0 + m;
        const bool ok = (row < NROW);
        const int g  = m >> 4;
        const int r  = m & 15;
        const int r7 = r & 7;
        const int rh = r >> 3;
        const int swz = (r7 >> 1) & 3;
        int offs[4];
#pragma unroll
        for (int j = 0; j < 4; ++j)
            offs[j] = (r7 * 4 + (j ^ swz)) * 4 + rh * 2 + h;
        const float4* pa4 = (const float4*)(g_agg + (size_t)(ok ? row : 0) * HID);
#pragma unroll
        for (int i = 0; i < 16; ++i) {
            float4 A0 = pa4[2 * i + h];
            if (!ok) A0 = make_float4(0, 0, 0, 0);
            uint32_t* rowp = A_s + (g * 16 + i) * 128;
            rowp[offs[0]] = f2tf32(A0.x);
            rowp[offs[1]] = f2tf32(A0.y);
            rowp[offs[2]] = f2tf32(A0.z);
            rowp[offs[3]] = f2tf32(A0.w);
        }
    }
    __syncthreads();

    const int lane = tid & 31;
    const int w    = tid >> 5;
    const int wm   = w & 3;
    const int wn   = w >> 2;
    const int ckr  = frag_chunk_r(lane) * 4;
    float acc[2][8][4];
#pragma unroll
    for (int g = 0; g < 2; ++g)
#pragma unroll
        for (int t = 0; t < 8; ++t)
#pragma unroll
            for (int q = 0; q < 4; ++q) acc[g][t][q] = 0.0f;

    const uint4* __restrict__ Bg4 = (const uint4*)g_W3p;

#pragma unroll
    for (int sp = 0; sp < 8; ++sp) {
        const int s0 = sp * 2;
        uint32_t a[2][2][4];
#pragma unroll
        for (int gg = 0; gg < 2; ++gg) {
            const int g = wm * 2 + gg;
            const uint4 v0 = *(const uint4*)(A_s + (g * 16 + s0) * 128 + ckr);
            const uint4 v1 = *(const uint4*)(A_s + (g * 16 + s0 + 1) * 128 + ckr);
            a[gg][0][0] = v0.x; a[gg][0][1] = v0.z; a[gg][0][2] = v0.y; a[gg][0][3] = v0.w;
            a[gg][1][0] = v1.x; a[gg][1][1] = v1.z; a[gg][1][2] = v1.y; a[gg][1][3] = v1.w;
        }
#pragma unroll
        for (int t = 0; t < 8; ++t) {
            const uint4 bv = __ldg(Bg4 + ((wn * 8 + t) * 8 + sp) * 32 + lane);
            mma_tf32(acc[0][t], a[0][0], bv.x, bv.y);
            mma_tf32(acc[1][t], a[1][0], bv.x, bv.y);
            mma_tf32(acc[0][t], a[0][1], bv.z, bv.w);
            mma_tf32(acc[1][t], a[1][1], bv.z, bv.w);
        }
    }

    const float4* b3p = (const float4*)(b3s + wn * 64 + 16 * (lane & 3));
    float4 b3q[4];
#pragma unroll
    for (int i = 0; i < 4; ++i) b3q[i] = b3p[i];

#pragma unroll
    for (int g = 0; g < 2; ++g) {
#pragma unroll
        for (int rh = 0; rh < 2; ++rh) {
            const int m   = wm * 32 + g * 16 + rh * 8 + (lane >> 2);
            const int row = r0 + m;
            if (row < NROW) {
                const float den = dens[m];
                const float inv = 1.0f / (den + 1e-12f);
                float* op = out + (size_t)row * COUT + wn * 64 + 16 * (lane & 3);
#pragma unroll
                for (int half = 0; half < 2; ++half) {
                    const int c = rh * 2 + half;
#pragma unroll
                    for (int tq = 0; tq < 2; ++tq) {
                        const float4 bb = b3q[half * 2 + tq];
                        float4 o = *(float4*)(op + half * 8 + tq * 4);
                        o.x += (acc[g][tq * 4 + 0][c] + den * bb.x) * inv;
                        o.y += (acc[g][tq * 4 + 1][c] + den * bb.y) * inv;
                        o.z += (acc[g][tq * 4 + 2][c] + den * bb.z) * inv;
                        o.w += (acc[g][tq * 4 + 3][c] + den * bb.w) * inv;
                        *(float4*)(op + half * 8 + tq * 4) = o;
                    }
                }
            }
        }
    }
}

// ---------------------------------------------------------------------------
extern "C" void kernel_launch(void* const* d_in, const int* in_sizes, int n_in,
                              void* d_out, int out_size) {
    const float* x   = (const float*)d_in[0];
    const float* pos = (const float*)d_in[1];
    const int*   ei  = (const int*)  d_in[2];
    const float* ew  = (const float*)d_in[3];
    const float* W1  = (const float*)d_in[4];
    const float* b1  = (const float*)d_in[5];
    const float* W2  = (const float*)d_in[6];
    const float* b2  = (const float*)d_in[7];
    const float* W3  = (const float*)d_in[8];
    const float* b3  = (const float*)d_in[9];
    const float* Ws  = (const float*)d_in[10];
    const float* bs  = (const float*)d_in[11];
    float* out = (float*)d_out;

    uint32_t* w2pb; cudaGetSymbolAddress((void**)&w2pb, g_W2pb);
    uint32_t* w3p;  cudaGetSymbolAddress((void**)&w3p,  g_W3p);

    cudaFuncSetAttribute(edge_kernel,  cudaFuncAttributeMaxDynamicSharedMemorySize, EDGE_SMEM);
    cudaFuncSetAttribute(final_kernel, cudaFuncAttributeMaxDynamicSharedMemorySize, FIN_SMEM);

    w2prep_bf16<<<32, 256>>>(W2, w2pb);
    wprep_kernel<<<64, 256>>>(W3, w3p);
    precompute_kernel<<<NROW, HID>>>(x, pos, W1, b1, Ws, bs, out);
    edge_kernel<<<dim3(EE / TE, BB), 256, EDGE_SMEM>>>(ei, ew, b2);
    final_kernel<<<(NROW + 127) / 128, 256, FIN_SMEM>>>(b3, out);
}

// round 15
// speedup vs baseline: 1.2584x; 1.0380x over previous
#include <cuda_runtime.h>
#include <cstdint>

// Problem constants (fixed by the dataset)
#define NN   10000
#define EE   320000
#define BB   2
#define CINN 64
#define HID  128
#define COUT 128
#define TE   128          // edges per block (= M tile of the edge GEMM)
#define NROW (BB * NN)    // 20000 output rows

// Scratch (device globals: no allocations allowed)
__device__ float    g_a_dst[(size_t)NN * HID];        //  5.12 MB
__device__ float    g_a_src[(size_t)BB * NN * HID];   // 10.24 MB
__device__ float    g_agg  [(size_t)BB * NN * HID];   // 10.24 MB
__device__ float    g_den  [NN];
__device__ uint32_t g_W2pb [16 * 4 * 32 * 4];         // W2 bf16 b-frags (32KB)
__device__ uint32_t g_W3p  [16 * 8 * 32 * 4];         // W3 tf32 b-frags (64KB)

typedef unsigned long long u64;

// ---- packed f32x2 helpers ------------------------------------------------
__device__ __forceinline__ u64 pk2(float a, float b) {
    u64 r; asm("mov.b64 %0, {%1, %2};" : "=l"(r) : "f"(a), "f"(b)); return r;
}
__device__ __forceinline__ void upk2(u64 v, float& a, float& b) {
    asm("mov.b64 {%0, %1}, %2;" : "=f"(a), "=f"(b) : "l"(v));
}
__device__ __forceinline__ u64 fma2_(u64 a, u64 b, u64 c) {
    u64 d; asm("fma.rn.f32x2 %0, %1, %2, %3;" : "=l"(d) : "l"(a), "l"(b), "l"(c)); return d;
}
__device__ __forceinline__ float tanh_ap(float x) {
    float y; asm("tanh.approx.f32 %0, %1;" : "=f"(y) : "f"(x)); return y;
}
// Packed tanh-gelu: 6 packed FMAs + 2 MUFU per pair of values.
__device__ __forceinline__ u64 gelu2(u64 v) {
    const u64 Z    = pk2(0.0f, 0.0f);
    const u64 K01  = pk2(0.0356774081f, 0.0356774081f);   // k0*k1
    const u64 K0   = pk2(0.7978845608f, 0.7978845608f);
    const u64 HALF = pk2(0.5f, 0.5f);
    const u64 vv  = fma2_(v, v, Z);
    const u64 p   = fma2_(K01, vv, Z);
    const u64 k0v = fma2_(K0, v, Z);
    const u64 u   = fma2_(p, v, k0v);                     // k0(v + k1 v^3)
    float ux, uy; upk2(u, ux, uy);
    const u64 t = pk2(tanh_ap(ux), tanh_ap(uy));
    const u64 w = fma2_(HALF, t, HALF);
    return fma2_(v, w, Z);
}
__device__ __forceinline__ uint32_t f2tf32(float f) {
    uint32_t r; asm("cvt.rna.tf32.f32 %0, %1;" : "=r"(r) : "f"(f)); return r;
}
// pack {lo, hi} floats -> bf16x2 word (first PTX operand is the HIGH half)
__device__ __forceinline__ uint32_t bf2(float lo, float hi) {
    uint32_t r; asm("cvt.rn.bf16x2.f32 %0, %1, %2;" : "=r"(r) : "f"(hi), "f"(lo)); return r;
}
// mma m16n8k16 bf16 (A row frag a0..a3, B col frag b0,b1; f32 accum)
__device__ __forceinline__ void mma_bf16(float* d, uint32_t a0, uint32_t a1,
                                         uint32_t a2, uint32_t a3,
                                         uint32_t b0, uint32_t b1) {
    asm volatile("mma.sync.aligned.m16n8k16.row.col.f32.bf16.bf16.f32 "
                 "{%0,%1,%2,%3}, {%4,%5,%6,%7}, {%8,%9}, {%0,%1,%2,%3};"
                 : "+f"(d[0]), "+f"(d[1]), "+f"(d[2]), "+f"(d[3])
                 : "r"(a0), "r"(a1), "r"(a2), "r"(a3), "r"(b0), "r"(b1));
}
// mma m16n8k8 tf32 (final_kernel)
__device__ __forceinline__ void mma_tf32(float* d, const uint32_t* a, uint32_t b0, uint32_t b1) {
    asm volatile("mma.sync.aligned.m16n8k8.row.col.f32.tf32.tf32.f32 "
                 "{%0,%1,%2,%3}, {%4,%5,%6,%7}, {%8,%9}, {%0,%1,%2,%3};"
                 : "+f"(d[0]), "+f"(d[1]), "+f"(d[2]), "+f"(d[3])
                 : "r"(a[0]), "r"(a[1]), "r"(a[2]), "r"(a[3]), "r"(b0), "r"(b1));
}

// ---------------------------------------------------------------------------
// W2 bf16 fragment prep (transposed column labels):
//   uint4 (t, sp, l) = { b0(s=2sp), b1(2sp), b0(2sp+1), b1(2sp+1) }, s = k16 step
//   b_j(s) lane l = bf16x2 of W[k0][n], W[k0+1][n],
//     k0 = s*16 + j*8 + (l&3)*2 ;  n = (t>>3)*64 + (l>>2)*8 + (t&7)
// ---------------------------------------------------------------------------
__global__ void w2prep_bf16(const float* __restrict__ W, uint32_t* __restrict__ dst) {
    const int idx = blockIdx.x * blockDim.x + threadIdx.x;   // 0..8191
    const int q  = idx & 3;
    const int l  = (idx >> 2) & 31;
    const int sp = (idx >> 7) & 3;
    const int t  = idx >> 9;                                  // 0..15
    const int j  = q & 1;
    const int s  = sp * 2 + (q >> 1);
    const int k0 = s * 16 + j * 8 + (l & 3) * 2;
    const int n  = (t >> 3) * 64 + (l >> 2) * 8 + (t & 7);
    dst[idx] = bf2(W[k0 * HID + n], W[(k0 + 1) * HID + n]);
}

// ---------------------------------------------------------------------------
// W3 tf32 fragment prep (transposed labels)
// ---------------------------------------------------------------------------
__global__ void wprep_kernel(const float* __restrict__ W, uint32_t* __restrict__ dst) {
    const int idx = blockIdx.x * blockDim.x + threadIdx.x;   // 0..16383 words
    const int q  = idx & 3;
    const int l  = (idx >> 2) & 31;
    const int sp = (idx >> 7) & 7;
    const int t  = idx >> 10;                                 // 0..15
    const int j  = q & 1;
    const int s  = sp * 2 + (q >> 1);
    const int k  = s * 8 + j * 4 + (l & 3);
    const int n  = (t >> 3) * 64 + (l >> 2) * 8 + (t & 7);
    dst[idx] = f2tf32(W[k * HID + n]);
}

// ---------------------------------------------------------------------------
// Per-node precompute (also zeroes g_agg / g_den) — unchanged
// ---------------------------------------------------------------------------
__global__ void precompute_kernel(const float* __restrict__ x, const float* __restrict__ pos,
                                  const float* __restrict__ W1, const float* __restrict__ b1,
                                  const float* __restrict__ Ws, const float* __restrict__ bs,
                                  float* __restrict__ out) {
    const int blk = blockIdx.x;          // b*NN + n
    const int b   = blk / NN;
    const int n   = blk - b * NN;
    const int t   = threadIdx.x;         // 0..127
    __shared__ float xr[CINN];
    __shared__ float p3[3];
    if (t < CINN) xr[t] = x[(size_t)blk * CINN + t];
    if (t < 3)    p3[t] = pos[n * 3 + t];

    g_agg[(size_t)blk * HID + t] = 0.0f;
    if (b == 0 && t == 0) g_den[n] = 0.0f;
    __syncthreads();

    float s = b1[t];
#pragma unroll
    for (int j = 0; j < 3; ++j) s += p3[j] * W1[(3 + j) * HID + t];
#pragma unroll 8
    for (int c = 0; c < CINN; ++c) s += xr[c] * W1[(6 + c) * HID + t];
    g_a_src[(size_t)blk * HID + t] = s;

    if (b == 0) {
        float d = p3[0] * W1[0 * HID + t] + p3[1] * W1[1 * HID + t] + p3[2] * W1[2 * HID + t];
        g_a_dst[(size_t)n * HID + t] = d;
    }

    float sk = bs[t];
#pragma unroll 8
    for (int c = 0; c < CINN; ++c) sk += xr[c] * Ws[c * COUT + t];
    out[(size_t)blk * COUT + t] = sk;
}

// ---------------------------------------------------------------------------
// bf16 A-smem layout (32KB): row m (0..127) x 64 bf16x2 words (as R13):
//   stored(s,off,h) = s*8 + off*2 + h ; addr = m*64 + (SW ^ c(m)),
//   c(m) = ((m&3)<<3) | (((m>>2)&1)<<2)
// ---------------------------------------------------------------------------
__device__ __forceinline__ int frag_chunk_r(int lane) {   // final_kernel only
    return (lane >> 2) * 4 + ((lane & 3) ^ (((lane >> 2) >> 1) & 3));
}

// ---------------------------------------------------------------------------
// Edge kernel (mma.sync bf16 k16). 128 edges/block, 256 threads, 2 CTAs/SM.
// Fill: warp-per-edge; indices prefetched into registers (1 LDG + shfl),
// gathers issued in batches of 8 (MLP ~16).
// ---------------------------------------------------------------------------
#define EDGE_SMEM (32768 + 512 + 512 + 512)
__global__ void __launch_bounds__(256, 2)
edge_kernel(const int* __restrict__ eidx, const float* __restrict__ ew,
            const float* __restrict__ b2) {
    extern __shared__ char sm[];
    uint32_t* A_s  = (uint32_t*)sm;                 // [128 m][64 words]
    float*    b2s  = (float*)   (sm + 32768);
    float*    ews  = (float*)   (sm + 33280);
    int*      dsts = (int*)     (sm + 33792);
    const int tid = threadIdx.x;
    const int e0  = blockIdx.x * TE;
    const int b   = blockIdx.y;

    if (tid < TE) {
        b2s[tid]  = b2[tid];
        const float w = ew[e0 + tid];
        const int   d = eidx[EE + e0 + tid];
        ews[tid]  = w;
        dsts[tid] = d;
        if (b == 0) atomicAdd(&g_den[d], w);        // fused den kernel
    }

    // Fill A: warp-per-edge, register-prefetched indices, 8-deep load batches.
    {
        const int lane = tid & 31;
        const int w    = tid >> 5;
        const int eb   = e0 + w * 16;
        // lanes 0..15 hold src idx of iteration 'lane'; 16..31 hold dst idx.
        const int idxv = __ldg(eidx + eb + (lane & 15) + ((lane >> 4) ? EE : 0));
        const int W0 = 8 * (lane >> 2) + 4 * (lane & 1) + ((lane >> 1) & 1);
        const u64 ONE = pk2(1.0f, 1.0f);
#pragma unroll
        for (int it0 = 0; it0 < 16; it0 += 8) {
            float4 Dv[8], Sv[8];
#pragma unroll
            for (int j = 0; j < 8; ++j) {
                const int it = it0 + j;
                const int sv = __shfl_sync(0xffffffffu, idxv, it);
                const int dv = __shfl_sync(0xffffffffu, idxv, 16 + it);
                Dv[j] = __ldg((const float4*)(g_a_dst + (size_t)dv * HID) + lane);
                Sv[j] = __ldg((const float4*)(g_a_src + ((size_t)b * NN + sv) * HID) + lane);
            }
#pragma unroll
            for (int j = 0; j < 8; ++j) {
                const int m = w * 16 + it0 + j;
                const u64 g0 = gelu2(fma2_(pk2(Dv[j].x, Dv[j].y), ONE, pk2(Sv[j].x, Sv[j].y)));
                const u64 g1 = gelu2(fma2_(pk2(Dv[j].z, Dv[j].w), ONE, pk2(Sv[j].z, Sv[j].w)));
                float a0, a1, a2, a3; upk2(g0, a0, a1); upk2(g1, a2, a3);
                const int cm = ((m & 3) << 3) | (((m >> 2) & 1) << 2);
                uint32_t* rowp = A_s + m * 64;
                rowp[(W0 + 0) ^ cm] = bf2(a0, a1);
                rowp[(W0 + 2) ^ cm] = bf2(a2, a3);
            }
        }
    }
    __syncthreads();

    // GEMM: warp (wm, wn) -> edges [wm*32,+32), cols [wn*64,+64); k16 steps
    const int lane = tid & 31;
    const int w    = tid >> 5;
    const int wm   = w & 3;
    const int wn   = w >> 2;
    const int fv   = lane >> 2;                     // row-in-group 0..7
    const int foff = lane & 3;
    const int cv   = ((fv & 3) << 3) | ((fv >> 2) << 2);
    float acc[2][8][4];
#pragma unroll
    for (int g = 0; g < 2; ++g)
#pragma unroll
        for (int t = 0; t < 8; ++t)
#pragma unroll
            for (int q = 0; q < 4; ++q) acc[g][t][q] = 0.0f;

    const uint4* __restrict__ Bg4 = (const uint4*)g_W2pb;

#pragma unroll
    for (int sp = 0; sp < 4; ++sp) {
        uint4 bv[8];
#pragma unroll
        for (int t = 0; t < 8; ++t)
            bv[t] = __ldg(Bg4 + ((wn * 8 + t) * 4 + sp) * 32 + lane);
#pragma unroll
        for (int sh = 0; sh < 2; ++sh) {
            const int s = sp * 2 + sh;
            const int swrd = (s * 8 + foff * 2) ^ cv;
            uint2 va[2], vb[2];
#pragma unroll
            for (int gg = 0; gg < 2; ++gg) {
                const int R = wm * 32 + gg * 16 + fv;
                va[gg] = *(const uint2*)(A_s + R * 64 + swrd);          // {a0,a2}
                vb[gg] = *(const uint2*)(A_s + (R + 8) * 64 + swrd);    // {a1,a3}
            }
#pragma unroll
            for (int t = 0; t < 8; ++t) {
                const uint32_t b0 = sh ? bv[t].z : bv[t].x;
                const uint32_t b1 = sh ? bv[t].w : bv[t].y;
                mma_bf16(acc[0][t], va[0].x, vb[0].x, va[0].y, vb[0].y, b0, b1);
                mma_bf16(acc[1][t], va[1].x, vb[1].x, va[1].y, vb[1].y, b0, b1);
            }
        }
    }

    // Epilogue: packed gelu + red.global.add.v4 (transposed labels)
    const float4* b2p = (const float4*)(b2s + wn * 64 + 16 * (lane & 3));
    float4 b2q[4];
#pragma unroll
    for (int i = 0; i < 4; ++i) b2q[i] = b2p[i];
    const u64 ONE = pk2(1.0f, 1.0f);
    const u64 Z   = pk2(0.0f, 0.0f);

#pragma unroll
    for (int g = 0; g < 2; ++g) {
#pragma unroll
        for (int rh = 0; rh < 2; ++rh) {
            const int m   = wm * 32 + g * 16 + rh * 8 + (lane >> 2);
            const float wgt = ews[m];
            const u64 w2 = pk2(wgt, wgt);
            float* base = g_agg + ((size_t)b * NN + dsts[m]) * HID
                          + wn * 64 + 16 * (lane & 3);
#pragma unroll
            for (int half = 0; half < 2; ++half) {
                const int c = rh * 2 + half;
#pragma unroll
                for (int tq = 0; tq < 2; ++tq) {
                    const float4 bb = b2q[half * 2 + tq];
                    const u64 v01 = fma2_(pk2(acc[g][tq * 4 + 0][c], acc[g][tq * 4 + 1][c]),
                                          ONE, pk2(bb.x, bb.y));
                    const u64 v23 = fma2_(pk2(acc[g][tq * 4 + 2][c], acc[g][tq * 4 + 3][c]),
                                          ONE, pk2(bb.z, bb.w));
                    const u64 r01 = fma2_(gelu2(v01), w2, Z);
                    const u64 r23 = fma2_(gelu2(v23), w2, Z);
                    float r0, r1, r2, r3; upk2(r01, r0, r1); upk2(r23, r2, r3);
                    asm volatile("red.global.add.v4.f32 [%0], {%1,%2,%3,%4};"
                                 :: "l"(base + half * 8 + tq * 4),
                                    "f"(r0), "f"(r1), "f"(r2), "f"(r3) : "memory");
                }
            }
        }
    }
}

// ---------------------------------------------------------------------------
// Final kernel (tf32): out += (agg @ W3 + den*b3)/(den+eps) — unchanged
// ---------------------------------------------------------------------------
#define FIN_SMEM (65536 + 512 + 512)
__global__ void __launch_bounds__(256, 2)
final_kernel(const float* __restrict__ b3, float* __restrict__ out) {
    extern __shared__ char sm[];
    uint32_t* A_s  = (uint32_t*)sm;                 // [8 g][16 s][128 words]
    float*    b3s  = (float*)(sm + 65536);
    float*    dens = (float*)(sm + 66048);
    const int tid = threadIdx.x;
    const int r0  = blockIdx.x * 128;

    if (tid < 128) {
        b3s[tid] = b3[tid];
        const int row = r0 + tid;
        dens[tid] = (row < NROW) ? g_den[row % NN] : 0.0f;
    }

    {
        const int m   = tid >> 1;
        const int h   = tid & 1;
        const int row = r0 + m;
        const bool ok = (row < NROW);
        const int g  = m >> 4;
        const int r  = m & 15;
        const int r7 = r & 7;
        const int rh = r >> 3;
        const int swz = (r7 >> 1) & 3;
        int offs[4];
#pragma unroll
        for (int j = 0; j < 4; ++j)
            offs[j] = (r7 * 4 + (j ^ swz)) * 4 + rh * 2 + h;
        const float4* pa4 = (const float4*)(g_agg + (size_t)(ok ? row : 0) * HID);
#pragma unroll
        for (int i = 0; i < 16; ++i) {
            float4 A0 = pa4[2 * i + h];
            if (!ok) A0 = make_float4(0, 0, 0, 0);
            uint32_t* rowp = A_s + (g * 16 + i) * 128;
            rowp[offs[0]] = f2tf32(A0.x);
            rowp[offs[1]] = f2tf32(A0.y);
            rowp[offs[2]] = f2tf32(A0.z);
            rowp[offs[3]] = f2tf32(A0.w);
        }
    }
    __syncthreads();

    const int lane = tid & 31;
    const int w    = tid >> 5;
    const int wm   = w & 3;
    const int wn   = w >> 2;
    const int ckr  = frag_chunk_r(lane) * 4;
    float acc[2][8][4];
#pragma unroll
    for (int g = 0; g < 2; ++g)
#pragma unroll
        for (int t = 0; t < 8; ++t)
#pragma unroll
            for (int q = 0; q < 4; ++q) acc[g][t][q] = 0.0f;

    const uint4* __restrict__ Bg4 = (const uint4*)g_W3p;

#pragma unroll
    for (int sp = 0; sp < 8; ++sp) {
        const int s0 = sp * 2;
        uint32_t a[2][2][4];
#pragma unroll
        for (int gg = 0; gg < 2; ++gg) {
            const int g = wm * 2 + gg;
            const uint4 v0 = *(const uint4*)(A_s + (g * 16 + s0) * 128 + ckr);
            const uint4 v1 = *(const uint4*)(A_s + (g * 16 + s0 + 1) * 128 + ckr);
            a[gg][0][0] = v0.x; a[gg][0][1] = v0.z; a[gg][0][2] = v0.y; a[gg][0][3] = v0.w;
            a[gg][1][0] = v1.x; a[gg][1][1] = v1.z; a[gg][1][2] = v1.y; a[gg][1][3] = v1.w;
        }
#pragma unroll
        for (int t = 0; t < 8; ++t) {
            const uint4 bv = __ldg(Bg4 + ((wn * 8 + t) * 8 + sp) * 32 + lane);
            mma_tf32(acc[0][t], a[0][0], bv.x, bv.y);
            mma_tf32(acc[1][t], a[1][0], bv.x, bv.y);
            mma_tf32(acc[0][t], a[0][1], bv.z, bv.w);
            mma_tf32(acc[1][t], a[1][1], bv.z, bv.w);
        }
    }

    const float4* b3p = (const float4*)(b3s + wn * 64 + 16 * (lane & 3));
    float4 b3q[4];
#pragma unroll
    for (int i = 0; i < 4; ++i) b3q[i] = b3p[i];

#pragma unroll
    for (int g = 0; g < 2; ++g) {
#pragma unroll
        for (int rh = 0; rh < 2; ++rh) {
            const int m   = wm * 32 + g * 16 + rh * 8 + (lane >> 2);
            const int row = r0 + m;
            if (row < NROW) {
                const float den = dens[m];
                const float inv = 1.0f / (den + 1e-12f);
                float* op = out + (size_t)row * COUT + wn * 64 + 16 * (lane & 3);
#pragma unroll
                for (int half = 0; half < 2; ++half) {
                    const int c = rh * 2 + half;
#pragma unroll
                    for (int tq = 0; tq < 2; ++tq) {
                        const float4 bb = b3q[half * 2 + tq];
                        float4 o = *(float4*)(op + half * 8 + tq * 4);
                        o.x += (acc[g][tq * 4 + 0][c] + den * bb.x) * inv;
                        o.y += (acc[g][tq * 4 + 1][c] + den * bb.y) * inv;
                        o.z += (acc[g][tq * 4 + 2][c] + den * bb.z) * inv;
                        o.w += (acc[g][tq * 4 + 3][c] + den * bb.w) * inv;
                        *(float4*)(op + half * 8 + tq * 4) = o;
                    }
                }
            }
        }
    }
}

// ---------------------------------------------------------------------------
extern "C" void kernel_launch(void* const* d_in, const int* in_sizes, int n_in,
                              void* d_out, int out_size) {
    const float* x   = (const float*)d_in[0];
    const float* pos = (const float*)d_in[1];
    const int*   ei  = (const int*)  d_in[2];
    const float* ew  = (const float*)d_in[3];
    const float* W1  = (const float*)d_in[4];
    const float* b1  = (const float*)d_in[5];
    const float* W2  = (const float*)d_in[6];
    const float* b2  = (const float*)d_in[7];
    const float* W3  = (const float*)d_in[8];
    const float* b3  = (const float*)d_in[9];
    const float* Ws  = (const float*)d_in[10];
    const float* bs  = (const float*)d_in[11];
    float* out = (float*)d_out;

    uint32_t* w2pb; cudaGetSymbolAddress((void**)&w2pb, g_W2pb);
    uint32_t* w3p;  cudaGetSymbolAddress((void**)&w3p,  g_W3p);

    cudaFuncSetAttribute(edge_kernel,  cudaFuncAttributeMaxDynamicSharedMemorySize, EDGE_SMEM);
    cudaFuncSetAttribute(final_kernel, cudaFuncAttributeMaxDynamicSharedMemorySize, FIN_SMEM);

    w2prep_bf16<<<32, 256>>>(W2, w2pb);
    wprep_kernel<<<64, 256>>>(W3, w3p);
    precompute_kernel<<<NROW, HID>>>(x, pos, W1, b1, Ws, bs, out);
    edge_kernel<<<dim3(EE / TE, BB), 256, EDGE_SMEM>>>(ei, ew, b2);
    final_kernel<<<(NROW + 127) / 128, 256, FIN_SMEM>>>(b3, out);
}

// round 16
// speedup vs baseline: 1.4197x; 1.1282x over previous
#include <cuda_runtime.h>
#include <cstdint>

// Problem constants (fixed by the dataset)
#define NN   10000
#define EE   320000
#define BB   2
#define CINN 64
#define HID  128
#define COUT 128
#define TE   128          // edges per block (= M tile of the edge GEMM)
#define NROW (BB * NN)    // 20000 output rows

// Scratch (device globals: no allocations allowed)
__device__ float    g_a_dst[(size_t)NN * HID];        //  5.12 MB
__device__ float    g_a_src[(size_t)BB * NN * HID];   // 10.24 MB
__device__ float    g_agg  [(size_t)BB * NN * HID];   // 10.24 MB
__device__ float    g_den  [NN];
__device__ uint32_t g_W2pb [16 * 4 * 32 * 4];         // W2 bf16 b-frags (32KB)
__device__ uint32_t g_W3p  [16 * 8 * 32 * 4];         // W3 tf32 b-frags (64KB)
__device__ uint32_t g_W1p  [16 * 4 * 32 * 4];         // W1[6:70] tf32 b-frags K=64 (32KB)
__device__ uint32_t g_Wsp  [16 * 4 * 32 * 4];         // Ws tf32 b-frags K=64 (32KB)

typedef unsigned long long u64;

// ---- packed f32x2 helpers ------------------------------------------------
__device__ __forceinline__ u64 pk2(float a, float b) {
    u64 r; asm("mov.b64 %0, {%1, %2};" : "=l"(r) : "f"(a), "f"(b)); return r;
}
__device__ __forceinline__ void upk2(u64 v, float& a, float& b) {
    asm("mov.b64 {%0, %1}, %2;" : "=f"(a), "=f"(b) : "l"(v));
}
__device__ __forceinline__ u64 fma2_(u64 a, u64 b, u64 c) {
    u64 d; asm("fma.rn.f32x2 %0, %1, %2, %3;" : "=l"(d) : "l"(a), "l"(b), "l"(c)); return d;
}
__device__ __forceinline__ float tanh_ap(float x) {
    float y; asm("tanh.approx.f32 %0, %1;" : "=f"(y) : "f"(x)); return y;
}
// Packed tanh-gelu: 6 packed FMAs + 2 MUFU per pair of values.
__device__ __forceinline__ u64 gelu2(u64 v) {
    const u64 Z    = pk2(0.0f, 0.0f);
    const u64 K01  = pk2(0.0356774081f, 0.0356774081f);   // k0*k1
    const u64 K0   = pk2(0.7978845608f, 0.7978845608f);
    const u64 HALF = pk2(0.5f, 0.5f);
    const u64 vv  = fma2_(v, v, Z);
    const u64 p   = fma2_(K01, vv, Z);
    const u64 k0v = fma2_(K0, v, Z);
    const u64 u   = fma2_(p, v, k0v);                     // k0(v + k1 v^3)
    float ux, uy; upk2(u, ux, uy);
    const u64 t = pk2(tanh_ap(ux), tanh_ap(uy));
    const u64 w = fma2_(HALF, t, HALF);
    return fma2_(v, w, Z);
}
__device__ __forceinline__ uint32_t f2tf32(float f) {
    uint32_t r; asm("cvt.rna.tf32.f32 %0, %1;" : "=r"(r) : "f"(f)); return r;
}
// pack {lo, hi} floats -> bf16x2 word (first PTX operand is the HIGH half)
__device__ __forceinline__ uint32_t bf2(float lo, float hi) {
    uint32_t r; asm("cvt.rn.bf16x2.f32 %0, %1, %2;" : "=r"(r) : "f"(hi), "f"(lo)); return r;
}
// mma m16n8k16 bf16 (A row frag a0..a3, B col frag b0,b1; f32 accum)
__device__ __forceinline__ void mma_bf16(float* d, uint32_t a0, uint32_t a1,
                                         uint32_t a2, uint32_t a3,
                                         uint32_t b0, uint32_t b1) {
    asm volatile("mma.sync.aligned.m16n8k16.row.col.f32.bf16.bf16.f32 "
                 "{%0,%1,%2,%3}, {%4,%5,%6,%7}, {%8,%9}, {%0,%1,%2,%3};"
                 : "+f"(d[0]), "+f"(d[1]), "+f"(d[2]), "+f"(d[3])
                 : "r"(a0), "r"(a1), "r"(a2), "r"(a3), "r"(b0), "r"(b1));
}
// mma m16n8k8 tf32
__device__ __forceinline__ void mma_tf32(float* d, const uint32_t* a, uint32_t b0, uint32_t b1) {
    asm volatile("mma.sync.aligned.m16n8k8.row.col.f32.tf32.tf32.f32 "
                 "{%0,%1,%2,%3}, {%4,%5,%6,%7}, {%8,%9}, {%0,%1,%2,%3};"
                 : "+f"(d[0]), "+f"(d[1]), "+f"(d[2]), "+f"(d[3])
                 : "r"(a[0]), "r"(a[1]), "r"(a[2]), "r"(a[3]), "r"(b0), "r"(b1));
}

// ---------------------------------------------------------------------------
// W2 bf16 fragment prep (transposed column labels):
//   uint4 (t, sp, l) = { b0(s=2sp), b1(2sp), b0(2sp+1), b1(2sp+1) }, s = k16 step
//   b_j(s) lane l = bf16x2 of W[k0][n], W[k0+1][n],
//     k0 = s*16 + j*8 + (l&3)*2 ;  n = (t>>3)*64 + (l>>2)*8 + (t&7)
// ---------------------------------------------------------------------------
__global__ void w2prep_bf16(const float* __restrict__ W, uint32_t* __restrict__ dst) {
    const int idx = blockIdx.x * blockDim.x + threadIdx.x;   // 0..8191
    const int q  = idx & 3;
    const int l  = (idx >> 2) & 31;
    const int sp = (idx >> 7) & 3;
    const int t  = idx >> 9;                                  // 0..15
    const int j  = q & 1;
    const int s  = sp * 2 + (q >> 1);
    const int k0 = s * 16 + j * 8 + (l & 3) * 2;
    const int n  = (t >> 3) * 64 + (l >> 2) * 8 + (t & 7);
    dst[idx] = bf2(W[k0 * HID + n], W[(k0 + 1) * HID + n]);
}

// ---------------------------------------------------------------------------
// W3 tf32 fragment prep (K=128, transposed labels)
// ---------------------------------------------------------------------------
__global__ void wprep_kernel(const float* __restrict__ W, uint32_t* __restrict__ dst) {
    const int idx = blockIdx.x * blockDim.x + threadIdx.x;   // 0..16383 words
    const int q  = idx & 3;
    const int l  = (idx >> 2) & 31;
    const int sp = (idx >> 7) & 7;
    const int t  = idx >> 10;                                 // 0..15
    const int j  = q & 1;
    const int s  = sp * 2 + (q >> 1);
    const int k  = s * 8 + j * 4 + (l & 3);
    const int n  = (t >> 3) * 64 + (l >> 2) * 8 + (t & 7);
    dst[idx] = f2tf32(W[k * HID + n]);
}

// ---------------------------------------------------------------------------
// K=64 tf32 fragment prep (transposed labels); W row-major, leading dim 128.
//   b_j(s) = W[(row_off + s*8 + j*4 + (l&3))][n]
// ---------------------------------------------------------------------------
__global__ void wprep64_kernel(const float* __restrict__ W, int row_off,
                               uint32_t* __restrict__ dst) {
    const int idx = blockIdx.x * blockDim.x + threadIdx.x;   // 0..8191 words
    const int q  = idx & 3;
    const int l  = (idx >> 2) & 31;
    const int sp = (idx >> 7) & 3;
    const int t  = idx >> 9;                                  // 0..15
    const int j  = q & 1;
    const int s  = sp * 2 + (q >> 1);
    const int k  = s * 8 + j * 4 + (l & 3);
    const int n  = (t >> 3) * 64 + (l >> 2) * 8 + (t & 7);
    dst[idx] = f2tf32(W[(size_t)(row_off + k) * HID + n]);
}

// ---------------------------------------------------------------------------
// Swizzled fragment helpers
// ---------------------------------------------------------------------------
__device__ __forceinline__ int frag_chunk_r(int lane) {
    return (lane >> 2) * 4 + ((lane & 3) ^ (((lane >> 2) >> 1) & 3));
}

// ---------------------------------------------------------------------------
// Precompute (tf32 mma, K=64): per block 128 rows (b*NN+n), 256 threads.
//   GEMM1: acc = x @ W1[6:70]  -> a_src = acc + pos@W1[3:6] + b1
//          also a_dst = pos@W1[0:3] (b==0 rows) ; zero g_agg/g_den (fused)
//   GEMM2: acc = x @ Ws        -> out = acc + bs  (skip path; final adds)
// SMEM: A frags 32KB + pos3 1.5KB + W1[0:6] 3KB + b1/bs 1KB = 38.4KB
// ---------------------------------------------------------------------------
#define PRE_SMEM (32768 + 1536 + 3072 + 512 + 512)
__global__ void __launch_bounds__(256, 2)
precompute_mma(const float* __restrict__ x, const float* __restrict__ pos,
               const float* __restrict__ W1, const float* __restrict__ b1,
               const float* __restrict__ bs, float* __restrict__ out) {
    extern __shared__ char sm[];
    uint32_t* A_s  = (uint32_t*)sm;                 // [8 g][8 s][128 words]
    float*    pos3 = (float*)(sm + 32768);          // [128][3]
    float*    w16  = (float*)(sm + 34304);          // [6][128] first 6 W1 rows
    float*    b1s  = (float*)(sm + 37376);
    float*    bss  = (float*)(sm + 37888);
    const int tid = threadIdx.x;
    const int r0  = blockIdx.x * 128;

    if (tid < 128) {
        b1s[tid] = b1[tid];
        bss[tid] = bs[tid];
        const int row = r0 + tid;
        if (row < NROW) {
            const int n = row % NN;
            pos3[tid * 3 + 0] = pos[n * 3 + 0];
            pos3[tid * 3 + 1] = pos[n * 3 + 1];
            pos3[tid * 3 + 2] = pos[n * 3 + 2];
        }
        if (row < NN) g_den[row] = 0.0f;            // fused den zero
    } else {
        const int i = tid - 128;
#pragma unroll
        for (int j = 0; j < 6; ++j) w16[j * 128 + i] = W1[j * HID + i];
    }

    // Fill A frags from x rows (K=64; same layout family as final_kernel)
    {
        const int m   = tid >> 1;
        const int h   = tid & 1;
        const int row = r0 + m;
        const bool ok = (row < NROW);
        const int g  = m >> 4;
        const int r  = m & 15;
        const int r7 = r & 7;
        const int rh = r >> 3;
        const int swz = (r7 >> 1) & 3;
        int offs[4];
#pragma unroll
        for (int j = 0; j < 4; ++j)
            offs[j] = (r7 * 4 + (j ^ swz)) * 4 + rh * 2 + h;
        const float4* pa4 = (const float4*)(x + (size_t)(ok ? row : 0) * CINN);
#pragma unroll
        for (int i = 0; i < 8; ++i) {               // i = s step (0..7)
            float4 A0 = pa4[2 * i + h];
            if (!ok) A0 = make_float4(0, 0, 0, 0);
            uint32_t* rowp = A_s + (g * 8 + i) * 128;
            rowp[offs[0]] = f2tf32(A0.x);
            rowp[offs[1]] = f2tf32(A0.y);
            rowp[offs[2]] = f2tf32(A0.z);
            rowp[offs[3]] = f2tf32(A0.w);
        }
    }
    __syncthreads();

    const int lane = tid & 31;
    const int w    = tid >> 5;
    const int wm   = w & 3;
    const int wn   = w >> 2;
    const int ckr  = frag_chunk_r(lane) * 4;
    const int colb = wn * 64 + 16 * (lane & 3);
    float acc[2][8][4];

    // ---------------- GEMM1: x @ W1[6:70] ----------------
#pragma unroll
    for (int g = 0; g < 2; ++g)
#pragma unroll
        for (int t = 0; t < 8; ++t)
#pragma unroll
            for (int q = 0; q < 4; ++q) acc[g][t][q] = 0.0f;
    {
        const uint4* __restrict__ Bg4 = (const uint4*)g_W1p;
#pragma unroll
        for (int sp = 0; sp < 4; ++sp) {
            const int s0 = sp * 2;
            uint32_t a[2][2][4];
#pragma unroll
            for (int gg = 0; gg < 2; ++gg) {
                const int g = wm * 2 + gg;
                const uint4 v0 = *(const uint4*)(A_s + (g * 8 + s0) * 128 + ckr);
                const uint4 v1 = *(const uint4*)(A_s + (g * 8 + s0 + 1) * 128 + ckr);
                a[gg][0][0] = v0.x; a[gg][0][1] = v0.z; a[gg][0][2] = v0.y; a[gg][0][3] = v0.w;
                a[gg][1][0] = v1.x; a[gg][1][1] = v1.z; a[gg][1][2] = v1.y; a[gg][1][3] = v1.w;
            }
#pragma unroll
            for (int t = 0; t < 8; ++t) {
                const uint4 bv = __ldg(Bg4 + ((wn * 8 + t) * 4 + sp) * 32 + lane);
                mma_tf32(acc[0][t], a[0][0], bv.x, bv.y);
                mma_tf32(acc[1][t], a[1][0], bv.x, bv.y);
                mma_tf32(acc[0][t], a[0][1], bv.z, bv.w);
                mma_tf32(acc[1][t], a[1][1], bv.z, bv.w);
            }
        }
    }
    // Epilogue1: a_src / a_dst / agg-zero
#pragma unroll
    for (int g = 0; g < 2; ++g) {
#pragma unroll
        for (int rh = 0; rh < 2; ++rh) {
            const int m   = wm * 32 + g * 16 + rh * 8 + (lane >> 2);
            const int row = r0 + m;
            if (row < NROW) {
                const float p0 = pos3[m * 3 + 0];
                const float p1 = pos3[m * 3 + 1];
                const float p2 = pos3[m * 3 + 2];
                float* ap = g_a_src + (size_t)row * HID + colb;
                float* zp = g_agg  + (size_t)row * HID + colb;
                const bool isb0 = (row < NN);
                float* dp = g_a_dst + (size_t)(isb0 ? row : 0) * HID + colb;
                const float4 Z4 = make_float4(0, 0, 0, 0);
#pragma unroll
                for (int half = 0; half < 2; ++half) {
                    const int c  = rh * 2 + half;
#pragma unroll
                    for (int tq = 0; tq < 2; ++tq) {
                        const int co = half * 8 + tq * 4;
                        const float4 w3v = *(const float4*)(w16 + 3 * 128 + colb + co);
                        const float4 w4v = *(const float4*)(w16 + 4 * 128 + colb + co);
                        const float4 w5v = *(const float4*)(w16 + 5 * 128 + colb + co);
                        const float4 b1v = *(const float4*)(b1s + colb + co);
                        float4 o;
                        o.x = acc[g][tq * 4 + 0][c] + p0 * w3v.x + p1 * w4v.x + p2 * w5v.x + b1v.x;
                        o.y = acc[g][tq * 4 + 1][c] + p0 * w3v.y + p1 * w4v.y + p2 * w5v.y + b1v.y;
                        o.z = acc[g][tq * 4 + 2][c] + p0 * w3v.z + p1 * w4v.z + p2 * w5v.z + b1v.z;
                        o.w = acc[g][tq * 4 + 3][c] + p0 * w3v.w + p1 * w4v.w + p2 * w5v.w + b1v.w;
                        *(float4*)(ap + co) = o;
                        *(float4*)(zp + co) = Z4;               // fused agg zero
                        if (isb0) {
                            const float4 w0v = *(const float4*)(w16 + 0 * 128 + colb + co);
                            const float4 w1v = *(const float4*)(w16 + 1 * 128 + colb + co);
                            const float4 w2v = *(const float4*)(w16 + 2 * 128 + colb + co);
                            float4 d;
                            d.x = p0 * w0v.x + p1 * w1v.x + p2 * w2v.x;
                            d.y = p0 * w0v.y + p1 * w1v.y + p2 * w2v.y;
                            d.z = p0 * w0v.z + p1 * w1v.z + p2 * w2v.z;
                            d.w = p0 * w0v.w + p1 * w1v.w + p2 * w2v.w;
                            *(float4*)(dp + co) = d;
                        }
                    }
                }
            }
        }
    }

    // ---------------- GEMM2: x @ Ws (skip path) ----------------
#pragma unroll
    for (int g = 0; g < 2; ++g)
#pragma unroll
        for (int t = 0; t < 8; ++t)
#pragma unroll
            for (int q = 0; q < 4; ++q) acc[g][t][q] = 0.0f;
    {
        const uint4* __restrict__ Bg4 = (const uint4*)g_Wsp;
#pragma unroll
        for (int sp = 0; sp < 4; ++sp) {
            const int s0 = sp * 2;
            uint32_t a[2][2][4];
#pragma unroll
            for (int gg = 0; gg < 2; ++gg) {
                const int g = wm * 2 + gg;
                const uint4 v0 = *(const uint4*)(A_s + (g * 8 + s0) * 128 + ckr);
                const uint4 v1 = *(const uint4*)(A_s + (g * 8 + s0 + 1) * 128 + ckr);
                a[gg][0][0] = v0.x; a[gg][0][1] = v0.z; a[gg][0][2] = v0.y; a[gg][0][3] = v0.w;
                a[gg][1][0] = v1.x; a[gg][1][1] = v1.z; a[gg][1][2] = v1.y; a[gg][1][3] = v1.w;
            }
#pragma unroll
            for (int t = 0; t < 8; ++t) {
                const uint4 bv = __ldg(Bg4 + ((wn * 8 + t) * 4 + sp) * 32 + lane);
                mma_tf32(acc[0][t], a[0][0], bv.x, bv.y);
                mma_tf32(acc[1][t], a[1][0], bv.x, bv.y);
                mma_tf32(acc[0][t], a[0][1], bv.z, bv.w);
                mma_tf32(acc[1][t], a[1][1], bv.z, bv.w);
            }
        }
    }
    // Epilogue2: out = acc + bs
#pragma unroll
    for (int g = 0; g < 2; ++g) {
#pragma unroll
        for (int rh = 0; rh < 2; ++rh) {
            const int m   = wm * 32 + g * 16 + rh * 8 + (lane >> 2);
            const int row = r0 + m;
            if (row < NROW) {
                float* op = out + (size_t)row * COUT + colb;
#pragma unroll
                for (int half = 0; half < 2; ++half) {
                    const int c = rh * 2 + half;
#pragma unroll
                    for (int tq = 0; tq < 2; ++tq) {
                        const int co = half * 8 + tq * 4;
                        const float4 bv = *(const float4*)(bss + colb + co);
                        float4 o;
                        o.x = acc[g][tq * 4 + 0][c] + bv.x;
                        o.y = acc[g][tq * 4 + 1][c] + bv.y;
                        o.z = acc[g][tq * 4 + 2][c] + bv.z;
                        o.w = acc[g][tq * 4 + 3][c] + bv.w;
                        *(float4*)(op + co) = o;
                    }
                }
            }
        }
    }
}

// ---------------------------------------------------------------------------
// Edge kernel (mma.sync bf16 k16). 128 edges/block, 256 threads, 2 CTAs/SM.
// Fill: warp-per-edge; indices prefetched into registers (1 LDG + shfl),
// gathers issued in batches of 8 (MLP ~16). (unchanged from R15)
// ---------------------------------------------------------------------------
#define EDGE_SMEM (32768 + 512 + 512 + 512)
__global__ void __launch_bounds__(256, 2)
edge_kernel(const int* __restrict__ eidx, const float* __restrict__ ew,
            const float* __restrict__ b2) {
    extern __shared__ char sm[];
    uint32_t* A_s  = (uint32_t*)sm;                 // [128 m][64 words]
    float*    b2s  = (float*)   (sm + 32768);
    float*    ews  = (float*)   (sm + 33280);
    int*      dsts = (int*)     (sm + 33792);
    const int tid = threadIdx.x;
    const int e0  = blockIdx.x * TE;
    const int b   = blockIdx.y;

    if (tid < TE) {
        b2s[tid]  = b2[tid];
        const float w = ew[e0 + tid];
        const int   d = eidx[EE + e0 + tid];
        ews[tid]  = w;
        dsts[tid] = d;
        if (b == 0) atomicAdd(&g_den[d], w);        // fused den kernel
    }

    // Fill A: warp-per-edge, register-prefetched indices, 8-deep load batches.
    {
        const int lane = tid & 31;
        const int w    = tid >> 5;
        const int eb   = e0 + w * 16;
        const int idxv = __ldg(eidx + eb + (lane & 15) + ((lane >> 4) ? EE : 0));
        const int W0 = 8 * (lane >> 2) + 4 * (lane & 1) + ((lane >> 1) & 1);
        const u64 ONE = pk2(1.0f, 1.0f);
#pragma unroll
        for (int it0 = 0; it0 < 16; it0 += 8) {
            float4 Dv[8], Sv[8];
#pragma unroll
            for (int j = 0; j < 8; ++j) {
                const int it = it0 + j;
                const int sv = __shfl_sync(0xffffffffu, idxv, it);
                const int dv = __shfl_sync(0xffffffffu, idxv, 16 + it);
                Dv[j] = __ldg((const float4*)(g_a_dst + (size_t)dv * HID) + lane);
                Sv[j] = __ldg((const float4*)(g_a_src + ((size_t)b * NN + sv) * HID) + lane);
            }
#pragma unroll
            for (int j = 0; j < 8; ++j) {
                const int m = w * 16 + it0 + j;
                const u64 g0 = gelu2(fma2_(pk2(Dv[j].x, Dv[j].y), ONE, pk2(Sv[j].x, Sv[j].y)));
                const u64 g1 = gelu2(fma2_(pk2(Dv[j].z, Dv[j].w), ONE, pk2(Sv[j].z, Sv[j].w)));
                float a0, a1, a2, a3; upk2(g0, a0, a1); upk2(g1, a2, a3);
                const int cm = ((m & 3) << 3) | (((m >> 2) & 1) << 2);
                uint32_t* rowp = A_s + m * 64;
                rowp[(W0 + 0) ^ cm] = bf2(a0, a1);
                rowp[(W0 + 2) ^ cm] = bf2(a2, a3);
            }
        }
    }
    __syncthreads();

    // GEMM: warp (wm, wn) -> edges [wm*32,+32), cols [wn*64,+64); k16 steps
    const int lane = tid & 31;
    const int w    = tid >> 5;
    const int wm   = w & 3;
    const int wn   = w >> 2;
    const int fv   = lane >> 2;
    const int foff = lane & 3;
    const int cv   = ((fv & 3) << 3) | ((fv >> 2) << 2);
    float acc[2][8][4];
#pragma unroll
    for (int g = 0; g < 2; ++g)
#pragma unroll
        for (int t = 0; t < 8; ++t)
#pragma unroll
            for (int q = 0; q < 4; ++q) acc[g][t][q] = 0.0f;

    const uint4* __restrict__ Bg4 = (const uint4*)g_W2pb;

#pragma unroll
    for (int sp = 0; sp < 4; ++sp) {
        uint4 bv[8];
#pragma unroll
        for (int t = 0; t < 8; ++t)
            bv[t] = __ldg(Bg4 + ((wn * 8 + t) * 4 + sp) * 32 + lane);
#pragma unroll
        for (int sh = 0; sh < 2; ++sh) {
            const int s = sp * 2 + sh;
            const int swrd = (s * 8 + foff * 2) ^ cv;
            uint2 va[2], vb[2];
#pragma unroll
            for (int gg = 0; gg < 2; ++gg) {
                const int R = wm * 32 + gg * 16 + fv;
                va[gg] = *(const uint2*)(A_s + R * 64 + swrd);
                vb[gg] = *(const uint2*)(A_s + (R + 8) * 64 + swrd);
            }
#pragma unroll
            for (int t = 0; t < 8; ++t) {
                const uint32_t b0 = sh ? bv[t].z : bv[t].x;
                const uint32_t b1 = sh ? bv[t].w : bv[t].y;
                mma_bf16(acc[0][t], va[0].x, vb[0].x, va[0].y, vb[0].y, b0, b1);
                mma_bf16(acc[1][t], va[1].x, vb[1].x, va[1].y, vb[1].y, b0, b1);
            }
        }
    }

    // Epilogue: packed gelu + red.global.add.v4 (transposed labels)
    const float4* b2p = (const float4*)(b2s + wn * 64 + 16 * (lane & 3));
    float4 b2q[4];
#pragma unroll
    for (int i = 0; i < 4; ++i) b2q[i] = b2p[i];
    const u64 ONE = pk2(1.0f, 1.0f);
    const u64 Z   = pk2(0.0f, 0.0f);

#pragma unroll
    for (int g = 0; g < 2; ++g) {
#pragma unroll
        for (int rh = 0; rh < 2; ++rh) {
            const int m   = wm * 32 + g * 16 + rh * 8 + (lane >> 2);
            const float wgt = ews[m];
            const u64 w2 = pk2(wgt, wgt);
            float* base = g_agg + ((size_t)b * NN + dsts[m]) * HID
                          + wn * 64 + 16 * (lane & 3);
#pragma unroll
            for (int half = 0; half < 2; ++half) {
                const int c = rh * 2 + half;
#pragma unroll
                for (int tq = 0; tq < 2; ++tq) {
                    const float4 bb = b2q[half * 2 + tq];
                    const u64 v01 = fma2_(pk2(acc[g][tq * 4 + 0][c], acc[g][tq * 4 + 1][c]),
                                          ONE, pk2(bb.x, bb.y));
                    const u64 v23 = fma2_(pk2(acc[g][tq * 4 + 2][c], acc[g][tq * 4 + 3][c]),
                                          ONE, pk2(bb.z, bb.w));
                    const u64 r01 = fma2_(gelu2(v01), w2, Z);
                    const u64 r23 = fma2_(gelu2(v23), w2, Z);
                    float r0, r1, r2, r3; upk2(r01, r0, r1); upk2(r23, r2, r3);
                    asm volatile("red.global.add.v4.f32 [%0], {%1,%2,%3,%4};"
                                 :: "l"(base + half * 8 + tq * 4),
                                    "f"(r0), "f"(r1), "f"(r2), "f"(r3) : "memory");
                }
            }
        }
    }
}

// ---------------------------------------------------------------------------
// Final kernel (tf32): out += (agg @ W3 + den*b3)/(den+eps) — unchanged
// ---------------------------------------------------------------------------
#define FIN_SMEM (65536 + 512 + 512)
__global__ void __launch_bounds__(256, 2)
final_kernel(const float* __restrict__ b3, float* __restrict__ out) {
    extern __shared__ char sm[];
    uint32_t* A_s  = (uint32_t*)sm;                 // [8 g][16 s][128 words]
    float*    b3s  = (float*)(sm + 65536);
    float*    dens = (float*)(sm + 66048);
    const int tid = threadIdx.x;
    const int r0  = blockIdx.x * 128;

    if (tid < 128) {
        b3s[tid] = b3[tid];
        const int row = r0 + tid;
        dens[tid] = (row < NROW) ? g_den[row % NN] : 0.0f;
    }

    {
        const int m   = tid >> 1;
        const int h   = tid & 1;
        const int row = r0 + m;
        const bool ok = (row < NROW);
        const int g  = m >> 4;
        const int r  = m & 15;
        const int r7 = r & 7;
        const int rh = r >> 3;
        const int swz = (r7 >> 1) & 3;
        int offs[4];
#pragma unroll
        for (int j = 0; j < 4; ++j)
            offs[j] = (r7 * 4 + (j ^ swz)) * 4 + rh * 2 + h;
        const float4* pa4 = (const float4*)(g_agg + (size_t)(ok ? row : 0) * HID);
#pragma unroll
        for (int i = 0; i < 16; ++i) {
            float4 A0 = pa4[2 * i + h];
            if (!ok) A0 = make_float4(0, 0, 0, 0);
            uint32_t* rowp = A_s + (g * 16 + i) * 128;
            rowp[offs[0]] = f2tf32(A0.x);
            rowp[offs[1]] = f2tf32(A0.y);
            rowp[offs[2]] = f2tf32(A0.z);
            rowp[offs[3]] = f2tf32(A0.w);
        }
    }
    __syncthreads();

    const int lane = tid & 31;
    const int w    = tid >> 5;
    const int wm   = w & 3;
    const int wn   = w >> 2;
    const int ckr  = frag_chunk_r(lane) * 4;
    float acc[2][8][4];
#pragma unroll
    for (int g = 0; g < 2; ++g)
#pragma unroll
        for (int t = 0; t < 8; ++t)
#pragma unroll
            for (int q = 0; q < 4; ++q) acc[g][t][q] = 0.0f;

    const uint4* __restrict__ Bg4 = (const uint4*)g_W3p;

#pragma unroll
    for (int sp = 0; sp < 8; ++sp) {
        const int s0 = sp * 2;
        uint32_t a[2][2][4];
#pragma unroll
        for (int gg = 0; gg < 2; ++gg) {
            const int g = wm * 2 + gg;
            const uint4 v0 = *(const uint4*)(A_s + (g * 16 + s0) * 128 + ckr);
            const uint4 v1 = *(const uint4*)(A_s + (g * 16 + s0 + 1) * 128 + ckr);
            a[gg][0][0] = v0.x; a[gg][0][1] = v0.z; a[gg][0][2] = v0.y; a[gg][0][3] = v0.w;
            a[gg][1][0] = v1.x; a[gg][1][1] = v1.z; a[gg][1][2] = v1.y; a[gg][1][3] = v1.w;
        }
#pragma unroll
        for (int t = 0; t < 8; ++t) {
            const uint4 bv = __ldg(Bg4 + ((wn * 8 + t) * 8 + sp) * 32 + lane);
            mma_tf32(acc[0][t], a[0][0], bv.x, bv.y);
            mma_tf32(acc[1][t], a[1][0], bv.x, bv.y);
            mma_tf32(acc[0][t], a[0][1], bv.z, bv.w);
            mma_tf32(acc[1][t], a[1][1], bv.z, bv.w);
        }
    }

    const float4* b3p = (const float4*)(b3s + wn * 64 + 16 * (lane & 3));
    float4 b3q[4];
#pragma unroll
    for (int i = 0; i < 4; ++i) b3q[i] = b3p[i];

#pragma unroll
    for (int g = 0; g < 2; ++g) {
#pragma unroll
        for (int rh = 0; rh < 2; ++rh) {
            const int m   = wm * 32 + g * 16 + rh * 8 + (lane >> 2);
            const int row = r0 + m;
            if (row < NROW) {
                const float den = dens[m];
                const float inv = 1.0f / (den + 1e-12f);
                float* op = out + (size_t)row * COUT + wn * 64 + 16 * (lane & 3);
#pragma unroll
                for (int half = 0; half < 2; ++half) {
                    const int c = rh * 2 + half;
#pragma unroll
                    for (int tq = 0; tq < 2; ++tq) {
                        const float4 bb = b3q[half * 2 + tq];
                        float4 o = *(float4*)(op + half * 8 + tq * 4);
                        o.x += (acc[g][tq * 4 + 0][c] + den * bb.x) * inv;
                        o.y += (acc[g][tq * 4 + 1][c] + den * bb.y) * inv;
                        o.z += (acc[g][tq * 4 + 2][c] + den * bb.z) * inv;
                        o.w += (acc[g][tq * 4 + 3][c] + den * bb.w) * inv;
                        *(float4*)(op + half * 8 + tq * 4) = o;
                    }
                }
            }
        }
    }
}

// ---------------------------------------------------------------------------
extern "C" void kernel_launch(void* const* d_in, const int* in_sizes, int n_in,
                              void* d_out, int out_size) {
    const float* x   = (const float*)d_in[0];
    const float* pos = (const float*)d_in[1];
    const int*   ei  = (const int*)  d_in[2];
    const float* ew  = (const float*)d_in[3];
    const float* W1  = (const float*)d_in[4];
    const float* b1  = (const float*)d_in[5];
    const float* W2  = (const float*)d_in[6];
    const float* b2  = (const float*)d_in[7];
    const float* W3  = (const float*)d_in[8];
    const float* b3  = (const float*)d_in[9];
    const float* Ws  = (const float*)d_in[10];
    const float* bs  = (const float*)d_in[11];
    float* out = (float*)d_out;

    uint32_t* w2pb; cudaGetSymbolAddress((void**)&w2pb, g_W2pb);
    uint32_t* w3p;  cudaGetSymbolAddress((void**)&w3p,  g_W3p);
    uint32_t* w1p;  cudaGetSymbolAddress((void**)&w1p,  g_W1p);
    uint32_t* wsp;  cudaGetSymbolAddress((void**)&wsp,  g_Wsp);

    cudaFuncSetAttribute(edge_kernel,    cudaFuncAttributeMaxDynamicSharedMemorySize, EDGE_SMEM);
    cudaFuncSetAttribute(final_kernel,   cudaFuncAttributeMaxDynamicSharedMemorySize, FIN_SMEM);
    cudaFuncSetAttribute(precompute_mma, cudaFuncAttributeMaxDynamicSharedMemorySize, PRE_SMEM);

    w2prep_bf16<<<32, 256>>>(W2, w2pb);
    wprep_kernel<<<64, 256>>>(W3, w3p);
    wprep64_kernel<<<32, 256>>>(W1, 6, w1p);
    wprep64_kernel<<<32, 256>>>(Ws, 0, wsp);
    precompute_mma<<<(NROW + 127) / 128, 256, PRE_SMEM>>>(x, pos, W1, b1, bs, out);
    edge_kernel<<<dim3(EE / TE, BB), 256, EDGE_SMEM>>>(ei, ew, b2);
    final_kernel<<<(NROW + 127) / 128, 256, FIN_SMEM>>>(b3, out);
}

// round 17
// speedup vs baseline: 1.4515x; 1.0224x over previous
#include <cuda_runtime.h>
#include <cstdint>

// Problem constants (fixed by the dataset)
#define NN   10000
#define EE   320000
#define BB   2
#define CINN 64
#define HID  128
#define COUT 128
#define TE   128          // edges per block (= M tile of the edge GEMM)
#define NROW (BB * NN)    // 20000 output rows

// Scratch (device globals: no allocations allowed)
__device__ float    g_a_dst[(size_t)NN * HID];        //  5.12 MB
__device__ float    g_a_src[(size_t)BB * NN * HID];   // 10.24 MB
__device__ float    g_agg  [(size_t)BB * NN * HID];   // 10.24 MB
__device__ float    g_den  [NN];
__device__ uint32_t g_W2pb [16 * 4 * 32 * 4];         // W2 bf16 b-frags (32KB)
__device__ uint32_t g_W3p  [16 * 8 * 32 * 4];         // W3 tf32 b-frags (64KB)
__device__ uint32_t g_W1p  [16 * 4 * 32 * 4];         // W1[6:70] tf32 b-frags K=64 (32KB)
__device__ uint32_t g_Wsp  [16 * 4 * 32 * 4];         // Ws tf32 b-frags K=64 (32KB)

typedef unsigned long long u64;

// ---- packed f32x2 helpers ------------------------------------------------
__device__ __forceinline__ u64 pk2(float a, float b) {
    u64 r; asm("mov.b64 %0, {%1, %2};" : "=l"(r) : "f"(a), "f"(b)); return r;
}
__device__ __forceinline__ void upk2(u64 v, float& a, float& b) {
    asm("mov.b64 {%0, %1}, %2;" : "=f"(a), "=f"(b) : "l"(v));
}
__device__ __forceinline__ u64 fma2_(u64 a, u64 b, u64 c) {
    u64 d; asm("fma.rn.f32x2 %0, %1, %2, %3;" : "=l"(d) : "l"(a), "l"(b), "l"(c)); return d;
}
__device__ __forceinline__ float tanh_ap(float x) {
    float y; asm("tanh.approx.f32 %0, %1;" : "=f"(y) : "f"(x)); return y;
}
// Packed tanh-gelu: 6 packed FMAs + 2 MUFU per pair of values.
__device__ __forceinline__ u64 gelu2(u64 v) {
    const u64 Z    = pk2(0.0f, 0.0f);
    const u64 K01  = pk2(0.0356774081f, 0.0356774081f);   // k0*k1
    const u64 K0   = pk2(0.7978845608f, 0.7978845608f);
    const u64 HALF = pk2(0.5f, 0.5f);
    const u64 vv  = fma2_(v, v, Z);
    const u64 p   = fma2_(K01, vv, Z);
    const u64 k0v = fma2_(K0, v, Z);
    const u64 u   = fma2_(p, v, k0v);                     // k0(v + k1 v^3)
    float ux, uy; upk2(u, ux, uy);
    const u64 t = pk2(tanh_ap(ux), tanh_ap(uy));
    const u64 w = fma2_(HALF, t, HALF);
    return fma2_(v, w, Z);
}
__device__ __forceinline__ uint32_t f2tf32(float f) {
    uint32_t r; asm("cvt.rna.tf32.f32 %0, %1;" : "=r"(r) : "f"(f)); return r;
}
// pack {lo, hi} floats -> bf16x2 word (first PTX operand is the HIGH half)
__device__ __forceinline__ uint32_t bf2(float lo, float hi) {
    uint32_t r; asm("cvt.rn.bf16x2.f32 %0, %1, %2;" : "=r"(r) : "f"(hi), "f"(lo)); return r;
}
// mma m16n8k16 bf16 (A row frag a0..a3, B col frag b0,b1; f32 accum)
__device__ __forceinline__ void mma_bf16(float* d, uint32_t a0, uint32_t a1,
                                         uint32_t a2, uint32_t a3,
                                         uint32_t b0, uint32_t b1) {
    asm volatile("mma.sync.aligned.m16n8k16.row.col.f32.bf16.bf16.f32 "
                 "{%0,%1,%2,%3}, {%4,%5,%6,%7}, {%8,%9}, {%0,%1,%2,%3};"
                 : "+f"(d[0]), "+f"(d[1]), "+f"(d[2]), "+f"(d[3])
                 : "r"(a0), "r"(a1), "r"(a2), "r"(a3), "r"(b0), "r"(b1));
}
// mma m16n8k8 tf32
__device__ __forceinline__ void mma_tf32(float* d, const uint32_t* a, uint32_t b0, uint32_t b1) {
    asm volatile("mma.sync.aligned.m16n8k8.row.col.f32.tf32.tf32.f32 "
                 "{%0,%1,%2,%3}, {%4,%5,%6,%7}, {%8,%9}, {%0,%1,%2,%3};"
                 : "+f"(d[0]), "+f"(d[1]), "+f"(d[2]), "+f"(d[3])
                 : "r"(a[0]), "r"(a[1]), "r"(a[2]), "r"(a[3]), "r"(b0), "r"(b1));
}

// ---------------------------------------------------------------------------
// prep_all: ONE launch packing all four weight-fragment tables.
//   blocks [0,32)    : W2 -> bf16 k16 frags (transposed labels)
//   blocks [32,96)   : W3 -> tf32 k8 frags K=128
//   blocks [96,128)  : W1 rows 6..69 -> tf32 k8 frags K=64
//   blocks [128,160) : Ws -> tf32 k8 frags K=64
// ---------------------------------------------------------------------------
__global__ void prep_all(const float* __restrict__ W2, const float* __restrict__ W3,
                         const float* __restrict__ W1, const float* __restrict__ Ws,
                         uint32_t* __restrict__ w2pb, uint32_t* __restrict__ w3p,
                         uint32_t* __restrict__ w1p,  uint32_t* __restrict__ wsp) {
    const int blk = blockIdx.x;
    if (blk < 32) {
        // W2 bf16: idx 0..8191
        const int idx = blk * 256 + threadIdx.x;
        const int q  = idx & 3;
        const int l  = (idx >> 2) & 31;
        const int sp = (idx >> 7) & 3;
        const int t  = idx >> 9;
        const int j  = q & 1;
        const int s  = sp * 2 + (q >> 1);
        const int k0 = s * 16 + j * 8 + (l & 3) * 2;
        const int n  = (t >> 3) * 64 + (l >> 2) * 8 + (t & 7);
        w2pb[idx] = bf2(W2[k0 * HID + n], W2[(k0 + 1) * HID + n]);
    } else if (blk < 96) {
        // W3 tf32 K=128: idx 0..16383
        const int idx = (blk - 32) * 256 + threadIdx.x;
        const int q  = idx & 3;
        const int l  = (idx >> 2) & 31;
        const int sp = (idx >> 7) & 7;
        const int t  = idx >> 10;
        const int j  = q & 1;
        const int s  = sp * 2 + (q >> 1);
        const int k  = s * 8 + j * 4 + (l & 3);
        const int n  = (t >> 3) * 64 + (l >> 2) * 8 + (t & 7);
        w3p[idx] = f2tf32(W3[k * HID + n]);
    } else {
        // K=64 tf32: W1 (row_off 6) or Ws (row_off 0); idx 0..8191
        const bool isW1 = (blk < 128);
        const int idx = (blk - (isW1 ? 96 : 128)) * 256 + threadIdx.x;
        const int q  = idx & 3;
        const int l  = (idx >> 2) & 31;
        const int sp = (idx >> 7) & 3;
        const int t  = idx >> 9;
        const int j  = q & 1;
        const int s  = sp * 2 + (q >> 1);
        const int k  = s * 8 + j * 4 + (l & 3);
        const int n  = (t >> 3) * 64 + (l >> 2) * 8 + (t & 7);
        if (isW1) w1p[idx] = f2tf32(W1[(size_t)(6 + k) * HID + n]);
        else      wsp[idx] = f2tf32(Ws[(size_t)k * HID + n]);
    }
}

// ---------------------------------------------------------------------------
// Swizzled fragment helpers
// ---------------------------------------------------------------------------
__device__ __forceinline__ int frag_chunk_r(int lane) {
    return (lane >> 2) * 4 + ((lane & 3) ^ (((lane >> 2) >> 1) & 3));
}

// ---------------------------------------------------------------------------
// Precompute (tf32 mma, K=64): per block 128 rows (b*NN+n), 256 threads.
//   GEMM1: acc = x @ W1[6:70]  -> a_src = acc + pos@W1[3:6] + b1
//          also a_dst = pos@W1[0:3] (b==0 rows) ; zero g_agg/g_den (fused)
//   GEMM2: acc = x @ Ws        -> out = acc + bs  (skip path; final adds)
// ---------------------------------------------------------------------------
#define PRE_SMEM (32768 + 1536 + 3072 + 512 + 512)
__global__ void __launch_bounds__(256, 2)
precompute_mma(const float* __restrict__ x, const float* __restrict__ pos,
               const float* __restrict__ W1, const float* __restrict__ b1,
               const float* __restrict__ bs, float* __restrict__ out) {
    extern __shared__ char sm[];
    uint32_t* A_s  = (uint32_t*)sm;                 // [8 g][8 s][128 words]
    float*    pos3 = (float*)(sm + 32768);          // [128][3]
    float*    w16  = (float*)(sm + 34304);          // [6][128] first 6 W1 rows
    float*    b1s  = (float*)(sm + 37376);
    float*    bss  = (float*)(sm + 37888);
    const int tid = threadIdx.x;
    const int r0  = blockIdx.x * 128;

    if (tid < 128) {
        b1s[tid] = b1[tid];
        bss[tid] = bs[tid];
        const int row = r0 + tid;
        if (row < NROW) {
            const int n = row % NN;
            pos3[tid * 3 + 0] = pos[n * 3 + 0];
            pos3[tid * 3 + 1] = pos[n * 3 + 1];
            pos3[tid * 3 + 2] = pos[n * 3 + 2];
        }
        if (row < NN) g_den[row] = 0.0f;            // fused den zero
    } else {
        const int i = tid - 128;
#pragma unroll
        for (int j = 0; j < 6; ++j) w16[j * 128 + i] = W1[j * HID + i];
    }

    // Fill A frags from x rows (K=64)
    {
        const int m   = tid >> 1;
        const int h   = tid & 1;
        const int row = r0 + m;
        const bool ok = (row < NROW);
        const int g  = m >> 4;
        const int r  = m & 15;
        const int r7 = r & 7;
        const int rh = r >> 3;
        const int swz = (r7 >> 1) & 3;
        int offs[4];
#pragma unroll
        for (int j = 0; j < 4; ++j)
            offs[j] = (r7 * 4 + (j ^ swz)) * 4 + rh * 2 + h;
        const float4* pa4 = (const float4*)(x + (size_t)(ok ? row : 0) * CINN);
#pragma unroll
        for (int i = 0; i < 8; ++i) {               // i = s step (0..7)
            float4 A0 = pa4[2 * i + h];
            if (!ok) A0 = make_float4(0, 0, 0, 0);
            uint32_t* rowp = A_s + (g * 8 + i) * 128;
            rowp[offs[0]] = f2tf32(A0.x);
            rowp[offs[1]] = f2tf32(A0.y);
            rowp[offs[2]] = f2tf32(A0.z);
            rowp[offs[3]] = f2tf32(A0.w);
        }
    }
    __syncthreads();

    const int lane = tid & 31;
    const int w    = tid >> 5;
    const int wm   = w & 3;
    const int wn   = w >> 2;
    const int ckr  = frag_chunk_r(lane) * 4;
    const int colb = wn * 64 + 16 * (lane & 3);
    float acc[2][8][4];

    // ---------------- GEMM1: x @ W1[6:70] ----------------
#pragma unroll
    for (int g = 0; g < 2; ++g)
#pragma unroll
        for (int t = 0; t < 8; ++t)
#pragma unroll
            for (int q = 0; q < 4; ++q) acc[g][t][q] = 0.0f;
    {
        const uint4* __restrict__ Bg4 = (const uint4*)g_W1p;
#pragma unroll
        for (int sp = 0; sp < 4; ++sp) {
            const int s0 = sp * 2;
            uint32_t a[2][2][4];
#pragma unroll
            for (int gg = 0; gg < 2; ++gg) {
                const int g = wm * 2 + gg;
                const uint4 v0 = *(const uint4*)(A_s + (g * 8 + s0) * 128 + ckr);
                const uint4 v1 = *(const uint4*)(A_s + (g * 8 + s0 + 1) * 128 + ckr);
                a[gg][0][0] = v0.x; a[gg][0][1] = v0.z; a[gg][0][2] = v0.y; a[gg][0][3] = v0.w;
                a[gg][1][0] = v1.x; a[gg][1][1] = v1.z; a[gg][1][2] = v1.y; a[gg][1][3] = v1.w;
            }
#pragma unroll
            for (int t = 0; t < 8; ++t) {
                const uint4 bv = __ldg(Bg4 + ((wn * 8 + t) * 4 + sp) * 32 + lane);
                mma_tf32(acc[0][t], a[0][0], bv.x, bv.y);
                mma_tf32(acc[1][t], a[1][0], bv.x, bv.y);
                mma_tf32(acc[0][t], a[0][1], bv.z, bv.w);
                mma_tf32(acc[1][t], a[1][1], bv.z, bv.w);
            }
        }
    }
    // Epilogue1: a_src / a_dst / agg-zero
#pragma unroll
    for (int g = 0; g < 2; ++g) {
#pragma unroll
        for (int rh = 0; rh < 2; ++rh) {
            const int m   = wm * 32 + g * 16 + rh * 8 + (lane >> 2);
            const int row = r0 + m;
            if (row < NROW) {
                const float p0 = pos3[m * 3 + 0];
                const float p1 = pos3[m * 3 + 1];
                const float p2 = pos3[m * 3 + 2];
                float* ap = g_a_src + (size_t)row * HID + colb;
                float* zp = g_agg  + (size_t)row * HID + colb;
                const bool isb0 = (row < NN);
                float* dp = g_a_dst + (size_t)(isb0 ? row : 0) * HID + colb;
                const float4 Z4 = make_float4(0, 0, 0, 0);
#pragma unroll
                for (int half = 0; half < 2; ++half) {
                    const int c  = rh * 2 + half;
#pragma unroll
                    for (int tq = 0; tq < 2; ++tq) {
                        const int co = half * 8 + tq * 4;
                        const float4 w3v = *(const float4*)(w16 + 3 * 128 + colb + co);
                        const float4 w4v = *(const float4*)(w16 + 4 * 128 + colb + co);
                        const float4 w5v = *(const float4*)(w16 + 5 * 128 + colb + co);
                        const float4 b1v = *(const float4*)(b1s + colb + co);
                        float4 o;
                        o.x = acc[g][tq * 4 + 0][c] + p0 * w3v.x + p1 * w4v.x + p2 * w5v.x + b1v.x;
                        o.y = acc[g][tq * 4 + 1][c] + p0 * w3v.y + p1 * w4v.y + p2 * w5v.y + b1v.y;
                        o.z = acc[g][tq * 4 + 2][c] + p0 * w3v.z + p1 * w4v.z + p2 * w5v.z + b1v.z;
                        o.w = acc[g][tq * 4 + 3][c] + p0 * w3v.w + p1 * w4v.w + p2 * w5v.w + b1v.w;
                        *(float4*)(ap + co) = o;
                        *(float4*)(zp + co) = Z4;               // fused agg zero
                        if (isb0) {
                            const float4 w0v = *(const float4*)(w16 + 0 * 128 + colb + co);
                            const float4 w1v = *(const float4*)(w16 + 1 * 128 + colb + co);
                            const float4 w2v = *(const float4*)(w16 + 2 * 128 + colb + co);
                            float4 d;
                            d.x = p0 * w0v.x + p1 * w1v.x + p2 * w2v.x;
                            d.y = p0 * w0v.y + p1 * w1v.y + p2 * w2v.y;
                            d.z = p0 * w0v.z + p1 * w1v.z + p2 * w2v.z;
                            d.w = p0 * w0v.w + p1 * w1v.w + p2 * w2v.w;
                            *(float4*)(dp + co) = d;
                        }
                    }
                }
            }
        }
    }

    // ---------------- GEMM2: x @ Ws (skip path) ----------------
#pragma unroll
    for (int g = 0; g < 2; ++g)
#pragma unroll
        for (int t = 0; t < 8; ++t)
#pragma unroll
            for (int q = 0; q < 4; ++q) acc[g][t][q] = 0.0f;
    {
        const uint4* __restrict__ Bg4 = (const uint4*)g_Wsp;
#pragma unroll
        for (int sp = 0; sp < 4; ++sp) {
            const int s0 = sp * 2;
            uint32_t a[2][2][4];
#pragma unroll
            for (int gg = 0; gg < 2; ++gg) {
                const int g = wm * 2 + gg;
                const uint4 v0 = *(const uint4*)(A_s + (g * 8 + s0) * 128 + ckr);
                const uint4 v1 = *(const uint4*)(A_s + (g * 8 + s0 + 1) * 128 + ckr);
                a[gg][0][0] = v0.x; a[gg][0][1] = v0.z; a[gg][0][2] = v0.y; a[gg][0][3] = v0.w;
                a[gg][1][0] = v1.x; a[gg][1][1] = v1.z; a[gg][1][2] = v1.y; a[gg][1][3] = v1.w;
            }
#pragma unroll
            for (int t = 0; t < 8; ++t) {
                const uint4 bv = __ldg(Bg4 + ((wn * 8 + t) * 4 + sp) * 32 + lane);
                mma_tf32(acc[0][t], a[0][0], bv.x, bv.y);
                mma_tf32(acc[1][t], a[1][0], bv.x, bv.y);
                mma_tf32(acc[0][t], a[0][1], bv.z, bv.w);
                mma_tf32(acc[1][t], a[1][1], bv.z, bv.w);
            }
        }
    }
    // Epilogue2: out = acc + bs
#pragma unroll
    for (int g = 0; g < 2; ++g) {
#pragma unroll
        for (int rh = 0; rh < 2; ++rh) {
            const int m   = wm * 32 + g * 16 + rh * 8 + (lane >> 2);
            const int row = r0 + m;
            if (row < NROW) {
                float* op = out + (size_t)row * COUT + colb;
#pragma unroll
                for (int half = 0; half < 2; ++half) {
                    const int c = rh * 2 + half;
#pragma unroll
                    for (int tq = 0; tq < 2; ++tq) {
                        const int co = half * 8 + tq * 4;
                        const float4 bv = *(const float4*)(bss + colb + co);
                        float4 o;
                        o.x = acc[g][tq * 4 + 0][c] + bv.x;
                        o.y = acc[g][tq * 4 + 1][c] + bv.y;
                        o.z = acc[g][tq * 4 + 2][c] + bv.z;
                        o.w = acc[g][tq * 4 + 3][c] + bv.w;
                        *(float4*)(op + co) = o;
                    }
                }
            }
        }
    }
}

// ---------------------------------------------------------------------------
// Edge kernel (mma.sync bf16 k16). 128 edges/block, 256 threads, 2 CTAs/SM.
// Fill: warp-per-edge; indices prefetched into registers (1 LDG + shfl),
// gathers issued in batches of 8 (MLP ~16).
// ---------------------------------------------------------------------------
#define EDGE_SMEM (32768 + 512 + 512 + 512)
__global__ void __launch_bounds__(256, 2)
edge_kernel(const int* __restrict__ eidx, const float* __restrict__ ew,
            const float* __restrict__ b2) {
    extern __shared__ char sm[];
    uint32_t* A_s  = (uint32_t*)sm;                 // [128 m][64 words]
    float*    b2s  = (float*)   (sm + 32768);
    float*    ews  = (float*)   (sm + 33280);
    int*      dsts = (int*)     (sm + 33792);
    const int tid = threadIdx.x;
    const int e0  = blockIdx.x * TE;
    const int b   = blockIdx.y;

    if (tid < TE) {
        b2s[tid]  = b2[tid];
        const float w = ew[e0 + tid];
        const int   d = eidx[EE + e0 + tid];
        ews[tid]  = w;
        dsts[tid] = d;
        if (b == 0) atomicAdd(&g_den[d], w);        // fused den kernel
    }

    // Fill A: warp-per-edge, register-prefetched indices, 8-deep load batches.
    {
        const int lane = tid & 31;
        const int w    = tid >> 5;
        const int eb   = e0 + w * 16;
        const int idxv = __ldg(eidx + eb + (lane & 15) + ((lane >> 4) ? EE : 0));
        const int W0 = 8 * (lane >> 2) + 4 * (lane & 1) + ((lane >> 1) & 1);
        const u64 ONE = pk2(1.0f, 1.0f);
#pragma unroll
        for (int it0 = 0; it0 < 16; it0 += 8) {
            float4 Dv[8], Sv[8];
#pragma unroll
            for (int j = 0; j < 8; ++j) {
                const int it = it0 + j;
                const int sv = __shfl_sync(0xffffffffu, idxv, it);
                const int dv = __shfl_sync(0xffffffffu, idxv, 16 + it);
                Dv[j] = __ldg((const float4*)(g_a_dst + (size_t)dv * HID) + lane);
                Sv[j] = __ldg((const float4*)(g_a_src + ((size_t)b * NN + sv) * HID) + lane);
            }
#pragma unroll
            for (int j = 0; j < 8; ++j) {
                const int m = w * 16 + it0 + j;
                const u64 g0 = gelu2(fma2_(pk2(Dv[j].x, Dv[j].y), ONE, pk2(Sv[j].x, Sv[j].y)));
                const u64 g1 = gelu2(fma2_(pk2(Dv[j].z, Dv[j].w), ONE, pk2(Sv[j].z, Sv[j].w)));
                float a0, a1, a2, a3; upk2(g0, a0, a1); upk2(g1, a2, a3);
                const int cm = ((m & 3) << 3) | (((m >> 2) & 1) << 2);
                uint32_t* rowp = A_s + m * 64;
                rowp[(W0 + 0) ^ cm] = bf2(a0, a1);
                rowp[(W0 + 2) ^ cm] = bf2(a2, a3);
            }
        }
    }
    __syncthreads();

    // GEMM: warp (wm, wn) -> edges [wm*32,+32), cols [wn*64,+64); k16 steps
    const int lane = tid & 31;
    const int w    = tid >> 5;
    const int wm   = w & 3;
    const int wn   = w >> 2;
    const int fv   = lane >> 2;
    const int foff = lane & 3;
    const int cv   = ((fv & 3) << 3) | ((fv >> 2) << 2);
    float acc[2][8][4];
#pragma unroll
    for (int g = 0; g < 2; ++g)
#pragma unroll
        for (int t = 0; t < 8; ++t)
#pragma unroll
            for (int q = 0; q < 4; ++q) acc[g][t][q] = 0.0f;

    const uint4* __restrict__ Bg4 = (const uint4*)g_W2pb;

#pragma unroll
    for (int sp = 0; sp < 4; ++sp) {
        uint4 bv[8];
#pragma unroll
        for (int t = 0; t < 8; ++t)
            bv[t] = __ldg(Bg4 + ((wn * 8 + t) * 4 + sp) * 32 + lane);
#pragma unroll
        for (int sh = 0; sh < 2; ++sh) {
            const int s = sp * 2 + sh;
            const int swrd = (s * 8 + foff * 2) ^ cv;
            uint2 va[2], vb[2];
#pragma unroll
            for (int gg = 0; gg < 2; ++gg) {
                const int R = wm * 32 + gg * 16 + fv;
                va[gg] = *(const uint2*)(A_s + R * 64 + swrd);
                vb[gg] = *(const uint2*)(A_s + (R + 8) * 64 + swrd);
            }
#pragma unroll
            for (int t = 0; t < 8; ++t) {
                const uint32_t b0 = sh ? bv[t].z : bv[t].x;
                const uint32_t b1 = sh ? bv[t].w : bv[t].y;
                mma_bf16(acc[0][t], va[0].x, vb[0].x, va[0].y, vb[0].y, b0, b1);
                mma_bf16(acc[1][t], va[1].x, vb[1].x, va[1].y, vb[1].y, b0, b1);
            }
        }
    }

    // Epilogue: packed gelu + red.global.add.v4 (transposed labels)
    const float4* b2p = (const float4*)(b2s + wn * 64 + 16 * (lane & 3));
    float4 b2q[4];
#pragma unroll
    for (int i = 0; i < 4; ++i) b2q[i] = b2p[i];
    const u64 ONE = pk2(1.0f, 1.0f);
    const u64 Z   = pk2(0.0f, 0.0f);

#pragma unroll
    for (int g = 0; g < 2; ++g) {
#pragma unroll
        for (int rh = 0; rh < 2; ++rh) {
            const int m   = wm * 32 + g * 16 + rh * 8 + (lane >> 2);
            const float wgt = ews[m];
            const u64 w2 = pk2(wgt, wgt);
            float* base = g_agg + ((size_t)b * NN + dsts[m]) * HID
                          + wn * 64 + 16 * (lane & 3);
#pragma unroll
            for (int half = 0; half < 2; ++half) {
                const int c = rh * 2 + half;
#pragma unroll
                for (int tq = 0; tq < 2; ++tq) {
                    const float4 bb = b2q[half * 2 + tq];
                    const u64 v01 = fma2_(pk2(acc[g][tq * 4 + 0][c], acc[g][tq * 4 + 1][c]),
                                          ONE, pk2(bb.x, bb.y));
                    const u64 v23 = fma2_(pk2(acc[g][tq * 4 + 2][c], acc[g][tq * 4 + 3][c]),
                                          ONE, pk2(bb.z, bb.w));
                    const u64 r01 = fma2_(gelu2(v01), w2, Z);
                    const u64 r23 = fma2_(gelu2(v23), w2, Z);
                    float r0, r1, r2, r3; upk2(r01, r0, r1); upk2(r23, r2, r3);
                    asm volatile("red.global.add.v4.f32 [%0], {%1,%2,%3,%4};"
                                 :: "l"(base + half * 8 + tq * 4),
                                    "f"(r0), "f"(r1), "f"(r2), "f"(r3) : "memory");
                }
            }
        }
    }
}

// ---------------------------------------------------------------------------
// Final kernel (tf32): out += (agg @ W3 + den*b3)/(den+eps)
// ---------------------------------------------------------------------------
#define FIN_SMEM (65536 + 512 + 512)
__global__ void __launch_bounds__(256, 2)
final_kernel(const float* __restrict__ b3, float* __restrict__ out) {
    extern __shared__ char sm[];
    uint32_t* A_s  = (uint32_t*)sm;                 // [8 g][16 s][128 words]
    float*    b3s  = (float*)(sm + 65536);
    float*    dens = (float*)(sm + 66048);
    const int tid = threadIdx.x;
    const int r0  = blockIdx.x * 128;

    if (tid < 128) {
        b3s[tid] = b3[tid];
        const int row = r0 + tid;
        dens[tid] = (row < NROW) ? g_den[row % NN] : 0.0f;
    }

    {
        const int m   = tid >> 1;
        const int h   = tid & 1;
        const int row = r0 + m;
        const bool ok = (row < NROW);
        const int g  = m >> 4;
        const int r  = m & 15;
        const int r7 = r & 7;
        const int rh = r >> 3;
        const int swz = (r7 >> 1) & 3;
        int offs[4];
#pragma unroll
        for (int j = 0; j < 4; ++j)
            offs[j] = (r7 * 4 + (j ^ swz)) * 4 + rh * 2 + h;
        const float4* pa4 = (const float4*)(g_agg + (size_t)(ok ? row : 0) * HID);
#pragma unroll
        for (int i = 0; i < 16; ++i) {
            float4 A0 = pa4[2 * i + h];
            if (!ok) A0 = make_float4(0, 0, 0, 0);
            uint32_t* rowp = A_s + (g * 16 + i) * 128;
            rowp[offs[0]] = f2tf32(A0.x);
            rowp[offs[1]] = f2tf32(A0.y);
            rowp[offs[2]] = f2tf32(A0.z);
            rowp[offs[3]] = f2tf32(A0.w);
        }
    }
    __syncthreads();

    const int lane = tid & 31;
    const int w    = tid >> 5;
    const int wm   = w & 3;
    const int wn   = w >> 2;
    const int ckr  = frag_chunk_r(lane) * 4;
    float acc[2][8][4];
#pragma unroll
    for (int g = 0; g < 2; ++g)
#pragma unroll
        for (int t = 0; t < 8; ++t)
#pragma unroll
            for (int q = 0; q < 4; ++q) acc[g][t][q] = 0.0f;

    const uint4* __restrict__ Bg4 = (const uint4*)g_W3p;

#pragma unroll
    for (int sp = 0; sp < 8; ++sp) {
        const int s0 = sp * 2;
        uint32_t a[2][2][4];
#pragma unroll
        for (int gg = 0; gg < 2; ++gg) {
            const int g = wm * 2 + gg;
            const uint4 v0 = *(const uint4*)(A_s + (g * 16 + s0) * 128 + ckr);
            const uint4 v1 = *(const uint4*)(A_s + (g * 16 + s0 + 1) * 128 + ckr);
            a[gg][0][0] = v0.x; a[gg][0][1] = v0.z; a[gg][0][2] = v0.y; a[gg][0][3] = v0.w;
            a[gg][1][0] = v1.x; a[gg][1][1] = v1.z; a[gg][1][2] = v1.y; a[gg][1][3] = v1.w;
        }
#pragma unroll
        for (int t = 0; t < 8; ++t) {
            const uint4 bv = __ldg(Bg4 + ((wn * 8 + t) * 8 + sp) * 32 + lane);
            mma_tf32(acc[0][t], a[0][0], bv.x, bv.y);
            mma_tf32(acc[1][t], a[1][0], bv.x, bv.y);
            mma_tf32(acc[0][t], a[0][1], bv.z, bv.w);
            mma_tf32(acc[1][t], a[1][1], bv.z, bv.w);
        }
    }

    const float4* b3p = (const float4*)(b3s + wn * 64 + 16 * (lane & 3));
    float4 b3q[4];
#pragma unroll
    for (int i = 0; i < 4; ++i) b3q[i] = b3p[i];

#pragma unroll
    for (int g = 0; g < 2; ++g) {
#pragma unroll
        for (int rh = 0; rh < 2; ++rh) {
            const int m   = wm * 32 + g * 16 + rh * 8 + (lane >> 2);
            const int row = r0 + m;
            if (row < NROW) {
                const float den = dens[m];
                const float inv = 1.0f / (den + 1e-12f);
                float* op = out + (size_t)row * COUT + wn * 64 + 16 * (lane & 3);
#pragma unroll
                for (int half = 0; half < 2; ++half) {
                    const int c = rh * 2 + half;
#pragma unroll
                    for (int tq = 0; tq < 2; ++tq) {
                        const float4 bb = b3q[half * 2 + tq];
                        float4 o = *(float4*)(op + half * 8 + tq * 4);
                        o.x += (acc[g][tq * 4 + 0][c] + den * bb.x) * inv;
                        o.y += (acc[g][tq * 4 + 1][c] + den * bb.y) * inv;
                        o.z += (acc[g][tq * 4 + 2][c] + den * bb.z) * inv;
                        o.w += (acc[g][tq * 4 + 3][c] + den * bb.w) * inv;
                        *(float4*)(op + half * 8 + tq * 4) = o;
                    }
                }
            }
        }
    }
}

// ---------------------------------------------------------------------------
extern "C" void kernel_launch(void* const* d_in, const int* in_sizes, int n_in,
                              void* d_out, int out_size) {
    const float* x   = (const float*)d_in[0];
    const float* pos = (const float*)d_in[1];
    const int*   ei  = (const int*)  d_in[2];
    const float* ew  = (const float*)d_in[3];
    const float* W1  = (const float*)d_in[4];
    const float* b1  = (const float*)d_in[5];
    const float* W2  = (const float*)d_in[6];
    const float* b2  = (const float*)d_in[7];
    const float* W3  = (const float*)d_in[8];
    const float* b3  = (const float*)d_in[9];
    const float* Ws  = (const float*)d_in[10];
    const float* bs  = (const float*)d_in[11];
    float* out = (float*)d_out;

    uint32_t* w2pb; cudaGetSymbolAddress((void**)&w2pb, g_W2pb);
    uint32_t* w3p;  cudaGetSymbolAddress((void**)&w3p,  g_W3p);
    uint32_t* w1p;  cudaGetSymbolAddress((void**)&w1p,  g_W1p);
    uint32_t* wsp;  cudaGetSymbolAddress((void**)&wsp,  g_Wsp);

    cudaFuncSetAttribute(edge_kernel,    cudaFuncAttributeMaxDynamicSharedMemorySize, EDGE_SMEM);
    cudaFuncSetAttribute(final_kernel,   cudaFuncAttributeMaxDynamicSharedMemorySize, FIN_SMEM);
    cudaFuncSetAttribute(precompute_mma, cudaFuncAttributeMaxDynamicSharedMemorySize, PRE_SMEM);

    prep_all<<<160, 256>>>(W2, W3, W1, Ws, w2pb, w3p, w1p, wsp);
    precompute_mma<<<(NROW + 127) / 128, 256, PRE_SMEM>>>(x, pos, W1, b1, bs, out);
    edge_kernel<<<dim3(EE / TE, BB), 256, EDGE_SMEM>>>(ei, ew, b2);
    final_kernel<<<(NROW + 127) / 128, 256, FIN_SMEM>>>(b3, out);
}